// round 13
// baseline (speedup 1.0000x reference)
#include <cuda_runtime.h>
#include <cuda_bf16.h>
#include <math.h>
#include <stdint.h>

#define B_ 8
#define T_ 2048
#define V_ 1024
#define C_ 128
#define NB2 64   // 2*NB
#define S_ 64    // chunk size
#define NCH 32   // T_/S_
#define MT (B_ * T_)   // 16384

// ---------------- device scratch ----------------
__device__ unsigned short g_wth[3 * C_ * V_];        // W^T hi bf16, [N][K]
__device__ unsigned short g_wtl[3 * C_ * V_];        // W^T lo bf16
__device__ float g_logits[3 * C_ * V_];              // logits [N][V]
__device__ unsigned short g_bh[V_ * NB2];            // basis hi bf16 [N][K]
__device__ unsigned short g_bl[V_ * NB2];            // basis lo bf16
__device__ unsigned short g_r2h[(size_t)MT * NB2];   // r2 hi bf16 [M][64]
__device__ unsigned short g_r2l[(size_t)MT * NB2];   // r2 lo bf16
__device__ float g_qkv[(size_t)MT * 3 * C_];         // (B*T, 384)
__device__ float g_G[B_ * NCH * C_ * C_];            // per-chunk outer-product sums
__device__ float g_M[B_ * NCH * C_ * C_];            // chunk-boundary states

__device__ __forceinline__ float sigmoidf_(float x) { return 1.0f / (1.0f + expf(-x)); }

__device__ __forceinline__ void mma_bf16(float* c, const uint32_t* a, const uint32_t* b) {
    asm volatile(
        "mma.sync.aligned.m16n8k16.row.col.f32.bf16.bf16.f32 "
        "{%0,%1,%2,%3}, {%4,%5,%6,%7}, {%8,%9}, {%0,%1,%2,%3};"
        : "+f"(c[0]), "+f"(c[1]), "+f"(c[2]), "+f"(c[3])
        : "r"(a[0]), "r"(a[1]), "r"(a[2]), "r"(a[3]), "r"(b[0]), "r"(b[1]));
}

__device__ __forceinline__ uint32_t smem_to_u32(const void* p) {
    uint32_t a;
    asm("{ .reg .u64 t; cvta.to.shared.u64 t, %1; cvt.u32.u64 %0, t; }" : "=r"(a) : "l"(p));
    return a;
}

__device__ __forceinline__ void ldsm_x4(uint32_t* r, uint32_t addr) {
    asm volatile("ldmatrix.sync.aligned.m8n8.x4.shared.b16 {%0,%1,%2,%3}, [%4];"
                 : "=r"(r[0]), "=r"(r[1]), "=r"(r[2]), "=r"(r[3]) : "r"(addr));
}

#define CP_ASYNC16(dst, src) \
    asm volatile("cp.async.cg.shared.global [%0], [%1], 16;" :: "r"(dst), "l"(src))
#define CP_COMMIT() asm volatile("cp.async.commit_group;" ::: "memory")
#define CP_WAIT0()  asm volatile("cp.async.wait_group 0;" ::: "memory")
#define CP_WAIT1()  asm volatile("cp.async.wait_group 1;" ::: "memory")

// convert 8 fp32 -> packed bf16 hi (uint4) + lo (uint4)
__device__ __forceinline__ void cvt8_hilo(float4 a, float4 b, uint4& hi, uint4& lo) {
    float v[8] = {a.x, a.y, a.z, a.w, b.x, b.y, b.z, b.w};
    unsigned short h[8], l[8];
    #pragma unroll
    for (int u = 0; u < 8; u++) {
        __nv_bfloat16 hb = __float2bfloat16_rn(v[u]);
        __nv_bfloat16 lb = __float2bfloat16_rn(v[u] - __bfloat162float(hb));
        h[u] = __bfloat16_as_ushort(hb);
        l[u] = __bfloat16_as_ushort(lb);
    }
    hi = make_uint4((uint32_t)h[0] | ((uint32_t)h[1] << 16),
                    (uint32_t)h[2] | ((uint32_t)h[3] << 16),
                    (uint32_t)h[4] | ((uint32_t)h[5] << 16),
                    (uint32_t)h[6] | ((uint32_t)h[7] << 16));
    lo = make_uint4((uint32_t)l[0] | ((uint32_t)l[1] << 16),
                    (uint32_t)l[2] | ((uint32_t)l[3] << 16),
                    (uint32_t)l[4] | ((uint32_t)l[5] << 16),
                    (uint32_t)l[6] | ((uint32_t)l[7] << 16));
}

// ---------------- 0b) convert basis to bf16 hi/lo [N][K] ----------------
__global__ __launch_bounds__(256) void cvt_basis_kernel(const float* __restrict__ basis) {
    const size_t i = ((size_t)blockIdx.x * 256 + threadIdx.x) * 4;
    float4 v = *(const float4*)(basis + i);
    float vv[4] = {v.x, v.y, v.z, v.w};
    unsigned short h[4], l[4];
    #pragma unroll
    for (int u = 0; u < 4; u++) {
        __nv_bfloat16 hb = __float2bfloat16_rn(vv[u]);
        __nv_bfloat16 lb = __float2bfloat16_rn(vv[u] - __bfloat162float(hb));
        h[u] = __bfloat16_as_ushort(hb);
        l[u] = __bfloat16_as_ushort(lb);
    }
    *(uint2*)(g_bh + i) = make_uint2((uint32_t)h[0] | ((uint32_t)h[1] << 16),
                                     (uint32_t)h[2] | ((uint32_t)h[3] << 16));
    *(uint2*)(g_bl + i) = make_uint2((uint32_t)l[0] | ((uint32_t)l[1] << 16),
                                     (uint32_t)l[2] | ((uint32_t)l[3] << 16));
}

// ---------------- 1a) logits = coeffs @ basis^T, written [N][V] ----------------
__global__ __launch_bounds__(256) void logits_kernel(const float* __restrict__ basis,
                                                     const float* __restrict__ qc,
                                                     const float* __restrict__ kc,
                                                     const float* __restrict__ vc) {
    const int w = blockIdx.x;
    const int vb = blockIdx.y;
    const float* coef = (w == 0 ? qc : (w == 1 ? kc : vc));

    __shared__ float Cs[NB2][C_ + 4];
    __shared__ float Bs[NB2][C_ + 4];

    const int tid = threadIdx.x;
    const int lr = tid >> 1;
    const int lk = (tid & 1) * 32;

    #pragma unroll
    for (int u = 0; u < 8; u++) {
        const int k = lk + u * 4;
        float4 cv = *(const float4*)(coef + (size_t)lr * NB2 + k);
        Cs[k + 0][lr] = cv.x; Cs[k + 1][lr] = cv.y;
        Cs[k + 2][lr] = cv.z; Cs[k + 3][lr] = cv.w;
        float4 bv = *(const float4*)(basis + (size_t)(vb * 128 + lr) * NB2 + k);
        Bs[k + 0][lr] = bv.x; Bs[k + 1][lr] = bv.y;
        Bs[k + 2][lr] = bv.z; Bs[k + 3][lr] = bv.w;
    }
    __syncthreads();

    const int trow = tid >> 4;
    const int tcol = tid & 15;
    float acc[8][8] = {};
    #pragma unroll
    for (int kk = 0; kk < NB2; kk++) {
        float ar[8], br[8];
        *(float4*)&ar[0] = *(const float4*)&Cs[kk][trow * 8];
        *(float4*)&ar[4] = *(const float4*)&Cs[kk][trow * 8 + 4];
        *(float4*)&br[0] = *(const float4*)&Bs[kk][tcol * 8];
        *(float4*)&br[4] = *(const float4*)&Bs[kk][tcol * 8 + 4];
        #pragma unroll
        for (int i = 0; i < 8; i++)
            #pragma unroll
            for (int jn = 0; jn < 8; jn++)
                acc[i][jn] = fmaf(ar[i], br[jn], acc[i][jn]);
    }
    #pragma unroll
    for (int i = 0; i < 8; i++) {
        float* lrow = g_logits + (size_t)(w * C_ + trow * 8 + i) * V_ + vb * 128 + tcol * 8;
        *(float4*)(lrow)     = make_float4(acc[i][0], acc[i][1], acc[i][2], acc[i][3]);
        *(float4*)(lrow + 4) = make_float4(acc[i][4], acc[i][5], acc[i][6], acc[i][7]);
    }
}

// ---------------- 1b) column softmax over V, emit bf16 hi/lo ----------------
__global__ __launch_bounds__(256) void softmax_w_kernel() {
    const int n = blockIdx.x;
    const int tid = threadIdx.x;
    __shared__ float red[8];
    __shared__ float sval;

    float4 s4 = *(const float4*)(g_logits + (size_t)n * V_ + tid * 4);
    float s[4] = {s4.x, s4.y, s4.z, s4.w};

    float m = fmaxf(fmaxf(s[0], s[1]), fmaxf(s[2], s[3]));
    #pragma unroll
    for (int o = 16; o; o >>= 1) m = fmaxf(m, __shfl_xor_sync(0xffffffffu, m, o));
    if ((tid & 31) == 0) red[tid >> 5] = m;
    __syncthreads();
    if (tid < 8) {
        float t = red[tid];
        #pragma unroll
        for (int o = 4; o; o >>= 1) t = fmaxf(t, __shfl_xor_sync(0xffu, t, o));
        if (tid == 0) sval = t;
    }
    __syncthreads();
    const float M = sval;

    float e[4];
    float su = 0.f;
    #pragma unroll
    for (int u = 0; u < 4; u++) { e[u] = expf(s[u] - M); su += e[u]; }
    #pragma unroll
    for (int o = 16; o; o >>= 1) su += __shfl_xor_sync(0xffffffffu, su, o);
    if ((tid & 31) == 0) red[tid >> 5] = su;
    __syncthreads();
    if (tid < 8) {
        float t = red[tid];
        #pragma unroll
        for (int o = 4; o; o >>= 1) t += __shfl_xor_sync(0xffu, t, o);
        if (tid == 0) sval = t;
    }
    __syncthreads();
    const float inv = 1.0f / sval;

    unsigned short h[4], l[4];
    #pragma unroll
    for (int u = 0; u < 4; u++) {
        const float val = e[u] * inv;
        __nv_bfloat16 hb = __float2bfloat16_rn(val);
        __nv_bfloat16 lb = __float2bfloat16_rn(val - __bfloat162float(hb));
        h[u] = __bfloat16_as_ushort(hb);
        l[u] = __bfloat16_as_ushort(lb);
    }
    const size_t o = (size_t)n * V_ + tid * 4;
    *(uint2*)(g_wth + o) = make_uint2((uint32_t)h[0] | ((uint32_t)h[1] << 16),
                                      (uint32_t)h[2] | ((uint32_t)h[3] << 16));
    *(uint2*)(g_wtl + o) = make_uint2((uint32_t)l[0] | ((uint32_t)l[1] << 16),
                                      (uint32_t)l[2] | ((uint32_t)l[3] << 16));
}

// ---------------- 2) QKV GEMM: bf16x3 mma.sync + ldmatrix; A converted in-kernel from fp32 x ----------------
// R10 shape: BM=128, BN=128, 256 threads, 8 warps (warp tile 64x32), 3-stage.
// B tiles via cp.async from preconverted w; A tiles: LDG fp32 x -> cvt -> STS
// (register-staged one pipeline slot ahead; tensor pipe is the bound, issue slots idle).
#define QBUF 32768
__global__ __launch_bounds__(256) void qkv_mma_kernel(const float* __restrict__ x) {
    extern __shared__ char sm[];
    const uint32_t sbase = smem_to_u32(sm);
    const int tid = threadIdx.x;
    const int warp = tid >> 5, lane = tid & 31;
    const int bm = blockIdx.y * 128;
    const int bn = blockIdx.x * 128;
    const int wm = (warp >> 2) * 64;
    const int wn = (warp & 3) * 32;

    const int frow = tid >> 2;   // 0..63
    const int fkq = tid & 3;

    const int arow = lane & 15;
    const int akg = lane >> 4;
    const int fA = (arow >> 1) & 3;
    const int brow = ((lane >> 4) & 1) * 8 + (lane & 7);
    const int bkg = (lane >> 3) & 1;
    const int fB = (brow >> 1) & 3;

    float acc[4][4][4] = {};

    // B fill via cp.async
    auto fillB = [&](int stage, int c0) {
        const uint32_t nb = sbase + stage * QBUF;
        #pragma unroll
        for (int it = 0; it < 2; it++) {
            const int row = frow + it * 64;
            const uint32_t dst = nb + 16384 + row * 64 + ((fkq ^ ((row >> 1) & 3)) * 16);
            CP_ASYNC16(dst,        g_wth + (size_t)(bn + row) * V_ + c0 + fkq * 8);
            CP_ASYNC16(dst + 8192, g_wtl + (size_t)(bn + row) * V_ + c0 + fkq * 8);
        }
    };
    // A load+convert into registers
    auto loadA = [&](int c0, uint4* ah, uint4* al) {
        #pragma unroll
        for (int it = 0; it < 2; it++) {
            const int row = frow + it * 64;
            const float* src = x + (size_t)(bm + row) * V_ + c0 + fkq * 8;
            float4 a = __ldg((const float4*)src);
            float4 b = __ldg((const float4*)(src + 4));
            cvt8_hilo(a, b, ah[it], al[it]);
        }
    };
    // A store to stage
    auto storeA = [&](int stage, const uint4* ah, const uint4* al) {
        const uint32_t nb = sbase + stage * QBUF;
        #pragma unroll
        for (int it = 0; it < 2; it++) {
            const int row = frow + it * 64;
            const uint32_t dst = nb + row * 64 + ((fkq ^ ((row >> 1) & 3)) * 16);
            *(uint4*)(sm + (dst - sbase)) = ah[it];
            *(uint4*)(sm + (dst - sbase) + 8192) = al[it];
        }
    };

    uint4 ahr[2], alr[2];

    // prologue: stages 0,1
    loadA(0, ahr, alr);
    storeA(0, ahr, alr);
    fillB(0, 0);  CP_COMMIT();
    loadA(32, ahr, alr);
    storeA(1, ahr, alr);
    fillB(1, 32); CP_COMMIT();

    for (int ch = 0; ch < 32; ch++) {
        // prefetch A for ch+2 into registers (LDG latency hidden behind MMAs)
        const bool has_next = (ch + 2 < 32);
        if (has_next) loadA((ch + 2) * 32, ahr, alr);

        CP_WAIT1();
        __syncthreads();

        const uint32_t cb = sbase + (ch % 3) * QBUF;
        #pragma unroll
        for (int ks = 0; ks < 2; ks++) {
            uint32_t a_h[4][4], a_l[4][4];
            const uint32_t achunk = (uint32_t)(((ks * 2 + akg) ^ fA) * 16);
            #pragma unroll
            for (int mi = 0; mi < 4; mi++) {
                const uint32_t aaddr = cb + (uint32_t)((wm + mi * 16 + arow) * 64) + achunk;
                ldsm_x4(a_h[mi], aaddr);
                ldsm_x4(a_l[mi], aaddr + 8192);
            }
            uint32_t b_h[4][2], b_l[4][2];
            const uint32_t bchunk = (uint32_t)(((ks * 2 + bkg) ^ fB) * 16);
            #pragma unroll
            for (int nip = 0; nip < 2; nip++) {
                const uint32_t baddr = cb + 16384 +
                    (uint32_t)((wn + nip * 16 + brow) * 64) + bchunk;
                uint32_t rh[4], rl[4];
                ldsm_x4(rh, baddr);
                ldsm_x4(rl, baddr + 8192);
                b_h[nip * 2 + 0][0] = rh[0]; b_h[nip * 2 + 0][1] = rh[1];
                b_h[nip * 2 + 1][0] = rh[2]; b_h[nip * 2 + 1][1] = rh[3];
                b_l[nip * 2 + 0][0] = rl[0]; b_l[nip * 2 + 0][1] = rl[1];
                b_l[nip * 2 + 1][0] = rl[2]; b_l[nip * 2 + 1][1] = rl[3];
            }
            #pragma unroll
            for (int mi = 0; mi < 4; mi++)
                #pragma unroll
                for (int ni = 0; ni < 4; ni++) {
                    mma_bf16(acc[mi][ni], a_l[mi], b_h[ni]);
                    mma_bf16(acc[mi][ni], a_h[mi], b_l[ni]);
                    mma_bf16(acc[mi][ni], a_h[mi], b_h[ni]);
                }
        }

        __syncthreads();
        if (has_next) {
            storeA((ch + 2) % 3, ahr, alr);
            fillB((ch + 2) % 3, (ch + 2) * 32);
        }
        CP_COMMIT();   // empty group when no fill keeps wait_group invariant
    }

    const int g = lane >> 2, tg = lane & 3;
    #pragma unroll
    for (int mi = 0; mi < 4; mi++) {
        const int r0 = bm + wm + mi * 16 + g;
        #pragma unroll
        for (int ni = 0; ni < 4; ni++) {
            const int col = bn + wn + ni * 8 + tg * 2;
            *(float2*)(g_qkv + (size_t)r0 * (3 * C_) + col) =
                make_float2(acc[mi][ni][0], acc[mi][ni][1]);
            *(float2*)(g_qkv + (size_t)(r0 + 8) * (3 * C_) + col) =
                make_float2(acc[mi][ni][2], acc[mi][ni][3]);
        }
    }
}

// ---------------- 3a) per-chunk outer-product sums, merged 128x128 ----------------
__global__ __launch_bounds__(256) void chunk_g_kernel(const float* __restrict__ decay_ptr) {
    const int j = blockIdx.x;
    const int b = blockIdx.y;
    const float dec = sigmoidf_(decay_ptr[0]);
    const float l2d = log2f(dec);

    __shared__ float Ks[32][128];
    __shared__ float Vs[32][128];

    const int tid = threadIdx.x;
    const int trow = tid >> 4;
    const int tcol = tid & 15;
    const int r = tid >> 3;
    const int q8 = tid & 7;

    float acc[8][8] = {};
    const float* base = g_qkv + ((size_t)b * T_ + (size_t)j * S_) * (3 * C_);

    #pragma unroll
    for (int i0 = 0; i0 < S_; i0 += 32) {
        const float sc = exp2f((float)(S_ - 1 - (i0 + r)) * l2d);
        const float* row = base + (size_t)(i0 + r) * (3 * C_);
        #pragma unroll
        for (int u = 0; u < 4; u++) {
            const int c4 = (q8 + u * 8) * 4;
            float4 kv = *(const float4*)(row + C_ + c4);
            Ks[r][c4 + 0] = kv.x * sc;
            Ks[r][c4 + 1] = kv.y * sc;
            Ks[r][c4 + 2] = kv.z * sc;
            Ks[r][c4 + 3] = kv.w * sc;
            *(float4*)&Vs[r][c4] = *(const float4*)(row + 2 * C_ + c4);
        }
        __syncthreads();
        #pragma unroll
        for (int ii = 0; ii < 32; ii++) {
            float ar[8], br[8];
            *(float4*)&ar[0] = *(const float4*)&Ks[ii][trow * 8];
            *(float4*)&ar[4] = *(const float4*)&Ks[ii][trow * 8 + 4];
            *(float4*)&br[0] = *(const float4*)&Vs[ii][tcol * 8];
            *(float4*)&br[4] = *(const float4*)&Vs[ii][tcol * 8 + 4];
            #pragma unroll
            for (int m = 0; m < 8; m++)
                #pragma unroll
                for (int n = 0; n < 8; n++)
                    acc[m][n] = fmaf(ar[m], br[n], acc[m][n]);
        }
        __syncthreads();
    }

    float* gout = g_G + ((size_t)(b * NCH + j) * C_ * C_);
    #pragma unroll
    for (int m = 0; m < 8; m++) {
        float* grow = gout + (size_t)(trow * 8 + m) * C_ + tcol * 8;
        *(float4*)(grow)     = make_float4(acc[m][0], acc[m][1], acc[m][2], acc[m][3]);
        *(float4*)(grow + 4) = make_float4(acc[m][4], acc[m][5], acc[m][6], acc[m][7]);
    }
}

// ---------------- 3b) scan, float2 per thread ----------------
__global__ void scan_kernel(const float* __restrict__ decay_ptr) {
    const int idx = blockIdx.x * blockDim.x + threadIdx.x;  // 0..65535
    const int b = idx >> 13;
    const int e2 = idx & 8191;
    const float dec = sigmoidf_(decay_ptr[0]);
    const float dS = exp2f((float)S_ * log2f(dec));

    const float2* G = (const float2*)(g_G + (size_t)b * NCH * C_ * C_) + e2;
    float2* M = (float2*)(g_M + (size_t)b * NCH * C_ * C_) + e2;

    float2 m = make_float2(0.f, 0.f);
    #pragma unroll
    for (int jb = 0; jb < NCH; jb += 8) {
        float2 buf[8];
        #pragma unroll
        for (int u = 0; u < 8; u++) buf[u] = G[(size_t)(jb + u) * 8192];
        #pragma unroll
        for (int u = 0; u < 8; u++) {
            M[(size_t)(jb + u) * 8192] = m;
            m.x = fmaf(dS, m.x, buf[u].x);
            m.y = fmaf(dS, m.y, buf[u].y);
        }
    }
}

// ---------------- 3c) retrieval per chunk + fused r2 = R @ oc ----------------
__global__ __launch_bounds__(256) void retr_kernel(const float* __restrict__ decay_ptr,
                                                   const float* __restrict__ oc) {
    const int j = blockIdx.x;
    const int b = blockIdx.y;
    const float dec = sigmoidf_(decay_ptr[0]);
    const float l2d = log2f(dec);

    __shared__ char buf[49152];
    float (*Qs)[64]  = (float(*)[64])(buf);
    float (*Ks2)[64] = (float(*)[64])(buf + 8192);
    float (*As)[64]  = (float(*)[64])(buf + 16384);
    float (*Vs)[128] = (float(*)[128])(buf + 32768);
    float* Rs = (float*)buf;

    const int tid = threadIdx.x;
    const float* base = g_qkv + ((size_t)b * T_ + (size_t)j * S_) * (3 * C_);

    {
        const int ti = tid >> 4;
        const int ts = tid & 15;
        const int li = tid >> 2;
        const int lp = tid & 3;

        float acc[4][4] = {};
        for (int c0 = 0; c0 < C_; c0 += 32) {
            #pragma unroll
            for (int u = 0; u < 2; u++) {
                int c = lp * 8 + u * 4;
                float4 qv = *(const float4*)(base + (size_t)li * (3 * C_) + c0 + c);
                Qs[c + 0][li] = qv.x; Qs[c + 1][li] = qv.y;
                Qs[c + 2][li] = qv.z; Qs[c + 3][li] = qv.w;
                float4 kv = *(const float4*)(base + (size_t)li * (3 * C_) + C_ + c0 + c);
                Ks2[c + 0][li] = kv.x; Ks2[c + 1][li] = kv.y;
                Ks2[c + 2][li] = kv.z; Ks2[c + 3][li] = kv.w;
            }
            __syncthreads();
            #pragma unroll
            for (int cc = 0; cc < 32; cc++) {
                float4 a4 = *(const float4*)&Qs[cc][ti * 4];
                float4 b4 = *(const float4*)&Ks2[cc][ts * 4];
                float ar[4] = {a4.x, a4.y, a4.z, a4.w};
                float br[4] = {b4.x, b4.y, b4.z, b4.w};
                #pragma unroll
                for (int m = 0; m < 4; m++)
                    #pragma unroll
                    for (int n = 0; n < 4; n++)
                        acc[m][n] = fmaf(ar[m], br[n], acc[m][n]);
            }
            __syncthreads();
        }
        #pragma unroll
        for (int m = 0; m < 4; m++) {
            const int i = ti * 4 + m;
            #pragma unroll
            for (int n = 0; n < 4; n++) {
                const int s = ts * 4 + n;
                float v = 0.f;
                if (s < i) v = acc[m][n] * exp2f((float)(i - 1 - s) * l2d);
                As[s][i] = v;
            }
        }
    }
    __syncthreads();

    const int ti2 = tid >> 4;
    const int td  = tid & 15;
    const int lr  = tid >> 3;
    const int lq  = tid & 7;

    float accA[4][8] = {};
    float accM[4][8] = {};

    for (int s0 = 0; s0 < S_; s0 += 32) {
        #pragma unroll
        for (int u = 0; u < 4; u++) {
            int c4 = lq + u * 8;
            *(float4*)&Vs[lr][c4 * 4] =
                *(const float4*)(base + (size_t)(s0 + lr) * (3 * C_) + 2 * C_ + c4 * 4);
        }
        __syncthreads();
        #pragma unroll
        for (int ss = 0; ss < 32; ss++) {
            float4 a4 = *(const float4*)&As[s0 + ss][ti2 * 4];
            float4 b0 = *(const float4*)&Vs[ss][td * 8];
            float4 b1 = *(const float4*)&Vs[ss][td * 8 + 4];
            float ar[4] = {a4.x, a4.y, a4.z, a4.w};
            float br[8] = {b0.x, b0.y, b0.z, b0.w, b1.x, b1.y, b1.z, b1.w};
            #pragma unroll
            for (int m = 0; m < 4; m++)
                #pragma unroll
                for (int n = 0; n < 8; n++)
                    accA[m][n] = fmaf(ar[m], br[n], accA[m][n]);
        }
        __syncthreads();
    }

    const float* Mbase = g_M + (size_t)(b * NCH + j) * C_ * C_;
    {
        const int li = tid >> 2;
        const int lp = tid & 3;
        for (int c0 = 0; c0 < C_; c0 += 32) {
            #pragma unroll
            for (int u = 0; u < 2; u++) {
                int c = lp * 8 + u * 4;
                float4 qv = *(const float4*)(base + (size_t)li * (3 * C_) + c0 + c);
                Qs[c + 0][li] = qv.x; Qs[c + 1][li] = qv.y;
                Qs[c + 2][li] = qv.z; Qs[c + 3][li] = qv.w;
            }
            #pragma unroll
            for (int u = 0; u < 4; u++) {
                int c4 = lq + u * 8;
                *(float4*)&Vs[lr][c4 * 4] =
                    *(const float4*)(Mbase + (size_t)(c0 + lr) * C_ + c4 * 4);
            }
            __syncthreads();
            #pragma unroll
            for (int cc = 0; cc < 32; cc++) {
                float4 a4 = *(const float4*)&Qs[cc][ti2 * 4];
                float4 b0 = *(const float4*)&Vs[cc][td * 8];
                float4 b1 = *(const float4*)&Vs[cc][td * 8 + 4];
                float ar[4] = {a4.x, a4.y, a4.z, a4.w};
                float br[8] = {b0.x, b0.y, b0.z, b0.w, b1.x, b1.y, b1.z, b1.w};
                #pragma unroll
                for (int m = 0; m < 4; m++)
                    #pragma unroll
                    for (int n = 0; n < 8; n++)
                        accM[m][n] = fmaf(ar[m], br[n], accM[m][n]);
            }
            __syncthreads();
        }
    }

    __syncthreads();
    #pragma unroll
    for (int m = 0; m < 4; m++) {
        const int i = ti2 * 4 + m;
        const float di = exp2f((float)i * l2d);
        #pragma unroll
        for (int n = 0; n < 8; n++)
            Rs[i * 132 + td * 8 + n] = fmaf(di, accM[m][n], accA[m][n]);
    }
    __syncthreads();

    {
        const int i0 = (tid >> 4) * 4;
        const int j0 = (tid & 15) * 4;
        float racc[4][4] = {};
        #pragma unroll 4
        for (int d4 = 0; d4 < 128; d4 += 4) {
            float4 a0 = *(const float4*)&Rs[(i0 + 0) * 132 + d4];
            float4 a1 = *(const float4*)&Rs[(i0 + 1) * 132 + d4];
            float4 a2 = *(const float4*)&Rs[(i0 + 2) * 132 + d4];
            float4 a3 = *(const float4*)&Rs[(i0 + 3) * 132 + d4];
            float am[4][4] = {{a0.x, a0.y, a0.z, a0.w},
                              {a1.x, a1.y, a1.z, a1.w},
                              {a2.x, a2.y, a2.z, a2.w},
                              {a3.x, a3.y, a3.z, a3.w}};
            #pragma unroll
            for (int dd = 0; dd < 4; dd++) {
                float4 bv = __ldg((const float4*)(oc + (size_t)(d4 + dd) * NB2 + j0));
                float br[4] = {bv.x, bv.y, bv.z, bv.w};
                #pragma unroll
                for (int ii = 0; ii < 4; ii++)
                    #pragma unroll
                    for (int jj = 0; jj < 4; jj++)
                        racc[ii][jj] = fmaf(am[ii][dd], br[jj], racc[ii][jj]);
            }
        }
        const size_t mbase = (size_t)b * T_ + (size_t)j * S_;
        #pragma unroll
        for (int ii = 0; ii < 4; ii++) {
            unsigned short h[4], l[4];
            #pragma unroll
            for (int jj = 0; jj < 4; jj++) {
                __nv_bfloat16 hb = __float2bfloat16_rn(racc[ii][jj]);
                __nv_bfloat16 lb = __float2bfloat16_rn(racc[ii][jj] - __bfloat162float(hb));
                h[jj] = __bfloat16_as_ushort(hb);
                l[jj] = __bfloat16_as_ushort(lb);
            }
            const size_t o = (mbase + i0 + ii) * NB2 + j0;
            *(uint2*)(g_r2h + o) = make_uint2((uint32_t)h[0] | ((uint32_t)h[1] << 16),
                                              (uint32_t)h[2] | ((uint32_t)h[3] << 16));
            *(uint2*)(g_r2l + o) = make_uint2((uint32_t)l[0] | ((uint32_t)l[1] << 16),
                                              (uint32_t)l[2] | ((uint32_t)l[3] << 16));
        }
    }
}

// ---------------- 4) out = r2 @ basis^T * scale, bf16x3 + ldmatrix + cp.async ----------------
__global__ __launch_bounds__(256) void out2_mma_kernel(float* __restrict__ Cout,
                                                       const float* __restrict__ scale_ptr) {
    extern __shared__ char sm[];
    const uint32_t sbase = smem_to_u32(sm);
    const int tid = threadIdx.x;
    const int warp = tid >> 5, lane = tid & 31;
    const int bm = blockIdx.y * 128;
    const int bn = blockIdx.x * 128;
    const int wm = (warp >> 2) * 64;
    const int wn = (warp & 3) * 32;

    const int frow = tid >> 2;
    const int fkq = tid & 3;

    const int arow = lane & 15;
    const int akg = lane >> 4;
    const int fA = (arow >> 1) & 3;
    const int brow = ((lane >> 4) & 1) * 8 + (lane & 7);
    const int bkg = (lane >> 3) & 1;
    const int fB = (brow >> 1) & 3;

    float acc[4][4][4] = {};

    auto fill = [&](int stage, int c0) {
        const uint32_t nb = sbase + stage * QBUF;
        #pragma unroll
        for (int it = 0; it < 2; it++) {
            const int row = frow + it * 64;
            const uint32_t dst = nb + row * 64 + ((fkq ^ ((row >> 1) & 3)) * 16);
            CP_ASYNC16(dst,         g_r2h + (size_t)(bm + row) * NB2 + c0 + fkq * 8);
            CP_ASYNC16(dst + 8192,  g_r2l + (size_t)(bm + row) * NB2 + c0 + fkq * 8);
            CP_ASYNC16(dst + 16384, g_bh + (size_t)(bn + row) * NB2 + c0 + fkq * 8);
            CP_ASYNC16(dst + 24576, g_bl + (size_t)(bn + row) * NB2 + c0 + fkq * 8);
        }
    };

    fill(0, 0);
    CP_COMMIT();

    for (int ch = 0; ch < 2; ch++) {
        if (ch + 1 < 2) { fill(ch + 1, 32); CP_COMMIT(); }
        if (ch == 0) { CP_WAIT1(); } else { CP_WAIT0(); }
        __syncthreads();

        const uint32_t cb = sbase + ch * QBUF;
        #pragma unroll
        for (int ks = 0; ks < 2; ks++) {
            uint32_t a_h[4][4], a_l[4][4];
            const uint32_t achunk = (uint32_t)(((ks * 2 + akg) ^ fA) * 16);
            #pragma unroll
            for (int mi = 0; mi < 4; mi++) {
                const uint32_t aaddr = cb + (uint32_t)((wm + mi * 16 + arow) * 64) + achunk;
                ldsm_x4(a_h[mi], aaddr);
                ldsm_x4(a_l[mi], aaddr + 8192);
            }
            uint32_t b_h[4][2], b_l[4][2];
            const uint32_t bchunk = (uint32_t)(((ks * 2 + bkg) ^ fB) * 16);
            #pragma unroll
            for (int nip = 0; nip < 2; nip++) {
                const uint32_t baddr = cb + 16384 +
                    (uint32_t)((wn + nip * 16 + brow) * 64) + bchunk;
                uint32_t rh[4], rl[4];
                ldsm_x4(rh, baddr);
                ldsm_x4(rl, baddr + 8192);
                b_h[nip * 2 + 0][0] = rh[0]; b_h[nip * 2 + 0][1] = rh[1];
                b_h[nip * 2 + 1][0] = rh[2]; b_h[nip * 2 + 1][1] = rh[3];
                b_l[nip * 2 + 0][0] = rl[0]; b_l[nip * 2 + 0][1] = rl[1];
                b_l[nip * 2 + 1][0] = rl[2]; b_l[nip * 2 + 1][1] = rl[3];
            }
            #pragma unroll
            for (int mi = 0; mi < 4; mi++)
                #pragma unroll
                for (int ni = 0; ni < 4; ni++) {
                    mma_bf16(acc[mi][ni], a_l[mi], b_h[ni]);
                    mma_bf16(acc[mi][ni], a_h[mi], b_l[ni]);
                    mma_bf16(acc[mi][ni], a_h[mi], b_h[ni]);
                }
        }
        __syncthreads();
    }

    const float sc = *scale_ptr;
    const int g = lane >> 2, tg = lane & 3;
    #pragma unroll
    for (int mi = 0; mi < 4; mi++) {
        const int r0 = bm + wm + mi * 16 + g;
        #pragma unroll
        for (int ni = 0; ni < 4; ni++) {
            const int col = bn + wn + ni * 8 + tg * 2;
            *(float2*)(Cout + (size_t)r0 * V_ + col) =
                make_float2(acc[mi][ni][0] * sc, acc[mi][ni][1] * sc);
            *(float2*)(Cout + (size_t)(r0 + 8) * V_ + col) =
                make_float2(acc[mi][ni][2] * sc, acc[mi][ni][3] * sc);
        }
    }
}

// ---------------- launch ----------------
extern "C" void kernel_launch(void* const* d_in, const int* in_sizes, int n_in,
                              void* d_out, int out_size) {
    const float* x      = (const float*)d_in[0];
    const float* basis  = (const float*)d_in[1];
    const float* qc     = (const float*)d_in[2];
    const float* kc     = (const float*)d_in[3];
    const float* vc     = (const float*)d_in[4];
    const float* oc     = (const float*)d_in[5];
    const float* decay  = (const float*)d_in[6];
    const float* oscale = (const float*)d_in[7];
    float* out = (float*)d_out;

    cudaFuncSetAttribute(qkv_mma_kernel, cudaFuncAttributeMaxDynamicSharedMemorySize, 3 * QBUF);
    cudaFuncSetAttribute(out2_mma_kernel, cudaFuncAttributeMaxDynamicSharedMemorySize, 2 * QBUF);

    cvt_basis_kernel<<<(V_ * NB2) / 1024, 256>>>(basis);
    logits_kernel<<<dim3(3, 8), 256>>>(basis, qc, kc, vc);
    softmax_w_kernel<<<3 * C_, 256>>>();
    qkv_mma_kernel<<<dim3(3, MT / 128), 256, 3 * QBUF>>>(x);
    chunk_g_kernel<<<dim3(NCH, B_), 256>>>(decay);
    scan_kernel<<<256, 256>>>(decay);
    retr_kernel<<<dim3(NCH, B_), 256>>>(decay, oc);
    out2_mma_kernel<<<dim3(V_ / 128, MT / 128), 256, 2 * QBUF>>>(out, oscale);
}

// round 14
// speedup vs baseline: 1.2158x; 1.2158x over previous
#include <cuda_runtime.h>
#include <cuda_fp16.h>
#include <math.h>
#include <stdint.h>

#define B_ 8
#define T_ 2048
#define V_ 1024
#define C_ 128
#define NB2 64   // 2*NB
#define S_ 64    // chunk size
#define NCH 32   // T_/S_
#define MT (B_ * T_)   // 16384

// ---------------- device scratch ----------------
__device__ unsigned short g_xh16[(size_t)MT * V_];   // x hi fp16, row-major [M][K]
__device__ unsigned short g_xl16[(size_t)MT * V_];   // x lo fp16
__device__ unsigned short g_wt[3 * C_ * V_];         // W^T fp16 (single), [N][K]
__device__ float g_logits[3 * C_ * V_];              // logits [N][V]
__device__ unsigned short g_bt[V_ * NB2];            // basis fp16 (single) [N][K]
__device__ unsigned short g_r2h[(size_t)MT * NB2];   // r2 hi fp16 [M][64]
__device__ unsigned short g_r2l[(size_t)MT * NB2];   // r2 lo fp16
__device__ float g_qkv[(size_t)MT * 3 * C_];         // (B*T, 384)
__device__ float g_G[B_ * NCH * C_ * C_];            // per-chunk outer-product sums
__device__ float g_M[B_ * NCH * C_ * C_];            // chunk-boundary states

__device__ __forceinline__ float sigmoidf_(float x) { return 1.0f / (1.0f + expf(-x)); }

__device__ __forceinline__ void mma_f16(float* c, const uint32_t* a, const uint32_t* b) {
    asm volatile(
        "mma.sync.aligned.m16n8k16.row.col.f32.f16.f16.f32 "
        "{%0,%1,%2,%3}, {%4,%5,%6,%7}, {%8,%9}, {%0,%1,%2,%3};"
        : "+f"(c[0]), "+f"(c[1]), "+f"(c[2]), "+f"(c[3])
        : "r"(a[0]), "r"(a[1]), "r"(a[2]), "r"(a[3]), "r"(b[0]), "r"(b[1]));
}

__device__ __forceinline__ uint32_t smem_to_u32(const void* p) {
    uint32_t a;
    asm("{ .reg .u64 t; cvta.to.shared.u64 t, %1; cvt.u32.u64 %0, t; }" : "=r"(a) : "l"(p));
    return a;
}

__device__ __forceinline__ void ldsm_x4(uint32_t* r, uint32_t addr) {
    asm volatile("ldmatrix.sync.aligned.m8n8.x4.shared.b16 {%0,%1,%2,%3}, [%4];"
                 : "=r"(r[0]), "=r"(r[1]), "=r"(r[2]), "=r"(r[3]) : "r"(addr));
}

#define CP_ASYNC16(dst, src) \
    asm volatile("cp.async.cg.shared.global [%0], [%1], 16;" :: "r"(dst), "l"(src))
#define CP_COMMIT() asm volatile("cp.async.commit_group;" ::: "memory")
#define CP_WAIT0()  asm volatile("cp.async.wait_group 0;" ::: "memory")
#define CP_WAIT1()  asm volatile("cp.async.wait_group 1;" ::: "memory")

// ---------------- 0a) convert x to fp16 hi/lo, row-major [M][K] ----------------
__global__ __launch_bounds__(256) void cvt_x_kernel(const float* __restrict__ x) {
    const size_t i = ((size_t)blockIdx.x * 256 + threadIdx.x) * 4;
    float4 v = *(const float4*)(x + i);
    float vv[4] = {v.x, v.y, v.z, v.w};
    unsigned short h[4], l[4];
    #pragma unroll
    for (int u = 0; u < 4; u++) {
        __half hb = __float2half_rn(vv[u]);
        __half lb = __float2half_rn(vv[u] - __half2float(hb));
        h[u] = __half_as_ushort(hb);
        l[u] = __half_as_ushort(lb);
    }
    *(uint2*)(g_xh16 + i) = make_uint2((uint32_t)h[0] | ((uint32_t)h[1] << 16),
                                       (uint32_t)h[2] | ((uint32_t)h[3] << 16));
    *(uint2*)(g_xl16 + i) = make_uint2((uint32_t)l[0] | ((uint32_t)l[1] << 16),
                                       (uint32_t)l[2] | ((uint32_t)l[3] << 16));
}

// ---------------- 0b) convert basis to fp16 [N][K] ----------------
__global__ __launch_bounds__(256) void cvt_basis_kernel(const float* __restrict__ basis) {
    const size_t i = ((size_t)blockIdx.x * 256 + threadIdx.x) * 4;
    float4 v = *(const float4*)(basis + i);
    float vv[4] = {v.x, v.y, v.z, v.w};
    unsigned short h[4];
    #pragma unroll
    for (int u = 0; u < 4; u++) h[u] = __half_as_ushort(__float2half_rn(vv[u]));
    *(uint2*)(g_bt + i) = make_uint2((uint32_t)h[0] | ((uint32_t)h[1] << 16),
                                     (uint32_t)h[2] | ((uint32_t)h[3] << 16));
}

// ---------------- 1a) logits = coeffs @ basis^T, written [N][V] ----------------
__global__ __launch_bounds__(256) void logits_kernel(const float* __restrict__ basis,
                                                     const float* __restrict__ qc,
                                                     const float* __restrict__ kc,
                                                     const float* __restrict__ vc) {
    const int w = blockIdx.x;
    const int vb = blockIdx.y;
    const float* coef = (w == 0 ? qc : (w == 1 ? kc : vc));

    __shared__ float Cs[NB2][C_ + 4];
    __shared__ float Bs[NB2][C_ + 4];

    const int tid = threadIdx.x;
    const int lr = tid >> 1;
    const int lk = (tid & 1) * 32;

    #pragma unroll
    for (int u = 0; u < 8; u++) {
        const int k = lk + u * 4;
        float4 cv = *(const float4*)(coef + (size_t)lr * NB2 + k);
        Cs[k + 0][lr] = cv.x; Cs[k + 1][lr] = cv.y;
        Cs[k + 2][lr] = cv.z; Cs[k + 3][lr] = cv.w;
        float4 bv = *(const float4*)(basis + (size_t)(vb * 128 + lr) * NB2 + k);
        Bs[k + 0][lr] = bv.x; Bs[k + 1][lr] = bv.y;
        Bs[k + 2][lr] = bv.z; Bs[k + 3][lr] = bv.w;
    }
    __syncthreads();

    const int trow = tid >> 4;
    const int tcol = tid & 15;
    float acc[8][8] = {};
    #pragma unroll
    for (int kk = 0; kk < NB2; kk++) {
        float ar[8], br[8];
        *(float4*)&ar[0] = *(const float4*)&Cs[kk][trow * 8];
        *(float4*)&ar[4] = *(const float4*)&Cs[kk][trow * 8 + 4];
        *(float4*)&br[0] = *(const float4*)&Bs[kk][tcol * 8];
        *(float4*)&br[4] = *(const float4*)&Bs[kk][tcol * 8 + 4];
        #pragma unroll
        for (int i = 0; i < 8; i++)
            #pragma unroll
            for (int jn = 0; jn < 8; jn++)
                acc[i][jn] = fmaf(ar[i], br[jn], acc[i][jn]);
    }
    #pragma unroll
    for (int i = 0; i < 8; i++) {
        float* lrow = g_logits + (size_t)(w * C_ + trow * 8 + i) * V_ + vb * 128 + tcol * 8;
        *(float4*)(lrow)     = make_float4(acc[i][0], acc[i][1], acc[i][2], acc[i][3]);
        *(float4*)(lrow + 4) = make_float4(acc[i][4], acc[i][5], acc[i][6], acc[i][7]);
    }
}

// ---------------- 1b) column softmax over V, emit fp16 [N][K] ----------------
__global__ __launch_bounds__(256) void softmax_w_kernel() {
    const int n = blockIdx.x;
    const int tid = threadIdx.x;
    __shared__ float red[8];
    __shared__ float sval;

    float4 s4 = *(const float4*)(g_logits + (size_t)n * V_ + tid * 4);
    float s[4] = {s4.x, s4.y, s4.z, s4.w};

    float m = fmaxf(fmaxf(s[0], s[1]), fmaxf(s[2], s[3]));
    #pragma unroll
    for (int o = 16; o; o >>= 1) m = fmaxf(m, __shfl_xor_sync(0xffffffffu, m, o));
    if ((tid & 31) == 0) red[tid >> 5] = m;
    __syncthreads();
    if (tid < 8) {
        float t = red[tid];
        #pragma unroll
        for (int o = 4; o; o >>= 1) t = fmaxf(t, __shfl_xor_sync(0xffu, t, o));
        if (tid == 0) sval = t;
    }
    __syncthreads();
    const float M = sval;

    float e[4];
    float su = 0.f;
    #pragma unroll
    for (int u = 0; u < 4; u++) { e[u] = expf(s[u] - M); su += e[u]; }
    #pragma unroll
    for (int o = 16; o; o >>= 1) su += __shfl_xor_sync(0xffffffffu, su, o);
    if ((tid & 31) == 0) red[tid >> 5] = su;
    __syncthreads();
    if (tid < 8) {
        float t = red[tid];
        #pragma unroll
        for (int o = 4; o; o >>= 1) t += __shfl_xor_sync(0xffu, t, o);
        if (tid == 0) sval = t;
    }
    __syncthreads();
    const float inv = 1.0f / sval;

    unsigned short h[4];
    #pragma unroll
    for (int u = 0; u < 4; u++)
        h[u] = __half_as_ushort(__float2half_rn(e[u] * inv));
    *(uint2*)(g_wt + (size_t)n * V_ + tid * 4) =
        make_uint2((uint32_t)h[0] | ((uint32_t)h[1] << 16),
                   (uint32_t)h[2] | ((uint32_t)h[3] << 16));
}

// ---------------- 2) QKV GEMM: fp16 2-term mma.sync + ldmatrix + 3-stage cp.async ----------------
// BM=128, BN=128, 256 threads, warp tile 64x32. Stage: Ah 8K | Al 8K | B 8K = 24 KB.
#define QKVBUF 24576
__global__ __launch_bounds__(256) void qkv_mma_kernel() {
    extern __shared__ char sm[];
    const uint32_t sbase = smem_to_u32(sm);
    const int tid = threadIdx.x;
    const int warp = tid >> 5, lane = tid & 31;
    const int bm = blockIdx.y * 128;
    const int bn = blockIdx.x * 128;
    const int wm = (warp >> 2) * 64;
    const int wn = (warp & 3) * 32;

    const int frow = tid >> 2;
    const int fkq = tid & 3;

    const int arow = lane & 15;
    const int akg = lane >> 4;
    const int fA = (arow >> 1) & 3;
    const int brow = ((lane >> 4) & 1) * 8 + (lane & 7);
    const int bkg = (lane >> 3) & 1;
    const int fB = (brow >> 1) & 3;

    float acc[4][4][4] = {};

    auto fill = [&](int stage, int c0) {
        const uint32_t nb = sbase + stage * QKVBUF;
        #pragma unroll
        for (int it = 0; it < 2; it++) {
            const int row = frow + it * 64;
            const uint32_t dst = nb + row * 64 + ((fkq ^ ((row >> 1) & 3)) * 16);
            CP_ASYNC16(dst,         g_xh16 + (size_t)(bm + row) * V_ + c0 + fkq * 8);
            CP_ASYNC16(dst + 8192,  g_xl16 + (size_t)(bm + row) * V_ + c0 + fkq * 8);
            CP_ASYNC16(dst + 16384, g_wt + (size_t)(bn + row) * V_ + c0 + fkq * 8);
        }
    };

    fill(0, 0);  CP_COMMIT();
    fill(1, 32); CP_COMMIT();

    for (int ch = 0; ch < 32; ch++) {
        CP_WAIT1();
        __syncthreads();

        const uint32_t cb = sbase + (ch % 3) * QKVBUF;
        #pragma unroll
        for (int ks = 0; ks < 2; ks++) {
            uint32_t a_h[4][4], a_l[4][4];
            const uint32_t achunk = (uint32_t)(((ks * 2 + akg) ^ fA) * 16);
            #pragma unroll
            for (int mi = 0; mi < 4; mi++) {
                const uint32_t aaddr = cb + (uint32_t)((wm + mi * 16 + arow) * 64) + achunk;
                ldsm_x4(a_h[mi], aaddr);
                ldsm_x4(a_l[mi], aaddr + 8192);
            }
            uint32_t b_f[4][2];
            const uint32_t bchunk = (uint32_t)(((ks * 2 + bkg) ^ fB) * 16);
            #pragma unroll
            for (int nip = 0; nip < 2; nip++) {
                const uint32_t baddr = cb + 16384 +
                    (uint32_t)((wn + nip * 16 + brow) * 64) + bchunk;
                uint32_t rh[4];
                ldsm_x4(rh, baddr);
                b_f[nip * 2 + 0][0] = rh[0]; b_f[nip * 2 + 0][1] = rh[1];
                b_f[nip * 2 + 1][0] = rh[2]; b_f[nip * 2 + 1][1] = rh[3];
            }
            #pragma unroll
            for (int mi = 0; mi < 4; mi++)
                #pragma unroll
                for (int ni = 0; ni < 4; ni++) {
                    mma_f16(acc[mi][ni], a_l[mi], b_f[ni]);
                    mma_f16(acc[mi][ni], a_h[mi], b_f[ni]);
                }
        }

        __syncthreads();
        if (ch + 2 < 32) fill((ch + 2) % 3, (ch + 2) * 32);
        CP_COMMIT();
    }

    const int g = lane >> 2, tg = lane & 3;
    #pragma unroll
    for (int mi = 0; mi < 4; mi++) {
        const int r0 = bm + wm + mi * 16 + g;
        #pragma unroll
        for (int ni = 0; ni < 4; ni++) {
            const int col = bn + wn + ni * 8 + tg * 2;
            *(float2*)(g_qkv + (size_t)r0 * (3 * C_) + col) =
                make_float2(acc[mi][ni][0], acc[mi][ni][1]);
            *(float2*)(g_qkv + (size_t)(r0 + 8) * (3 * C_) + col) =
                make_float2(acc[mi][ni][2], acc[mi][ni][3]);
        }
    }
}

// ---------------- 3a) per-chunk outer-product sums, merged 128x128 ----------------
__global__ __launch_bounds__(256) void chunk_g_kernel(const float* __restrict__ decay_ptr) {
    const int j = blockIdx.x;
    const int b = blockIdx.y;
    const float dec = sigmoidf_(decay_ptr[0]);
    const float l2d = log2f(dec);

    __shared__ float Ks[32][128];
    __shared__ float Vs[32][128];

    const int tid = threadIdx.x;
    const int trow = tid >> 4;
    const int tcol = tid & 15;
    const int r = tid >> 3;
    const int q8 = tid & 7;

    float acc[8][8] = {};
    const float* base = g_qkv + ((size_t)b * T_ + (size_t)j * S_) * (3 * C_);

    #pragma unroll
    for (int i0 = 0; i0 < S_; i0 += 32) {
        const float sc = exp2f((float)(S_ - 1 - (i0 + r)) * l2d);
        const float* row = base + (size_t)(i0 + r) * (3 * C_);
        #pragma unroll
        for (int u = 0; u < 4; u++) {
            const int c4 = (q8 + u * 8) * 4;
            float4 kv = *(const float4*)(row + C_ + c4);
            Ks[r][c4 + 0] = kv.x * sc;
            Ks[r][c4 + 1] = kv.y * sc;
            Ks[r][c4 + 2] = kv.z * sc;
            Ks[r][c4 + 3] = kv.w * sc;
            *(float4*)&Vs[r][c4] = *(const float4*)(row + 2 * C_ + c4);
        }
        __syncthreads();
        #pragma unroll
        for (int ii = 0; ii < 32; ii++) {
            float ar[8], br[8];
            *(float4*)&ar[0] = *(const float4*)&Ks[ii][trow * 8];
            *(float4*)&ar[4] = *(const float4*)&Ks[ii][trow * 8 + 4];
            *(float4*)&br[0] = *(const float4*)&Vs[ii][tcol * 8];
            *(float4*)&br[4] = *(const float4*)&Vs[ii][tcol * 8 + 4];
            #pragma unroll
            for (int m = 0; m < 8; m++)
                #pragma unroll
                for (int n = 0; n < 8; n++)
                    acc[m][n] = fmaf(ar[m], br[n], acc[m][n]);
        }
        __syncthreads();
    }

    float* gout = g_G + ((size_t)(b * NCH + j) * C_ * C_);
    #pragma unroll
    for (int m = 0; m < 8; m++) {
        float* grow = gout + (size_t)(trow * 8 + m) * C_ + tcol * 8;
        *(float4*)(grow)     = make_float4(acc[m][0], acc[m][1], acc[m][2], acc[m][3]);
        *(float4*)(grow + 4) = make_float4(acc[m][4], acc[m][5], acc[m][6], acc[m][7]);
    }
}

// ---------------- 3b) scan, float2 per thread ----------------
__global__ void scan_kernel(const float* __restrict__ decay_ptr) {
    const int idx = blockIdx.x * blockDim.x + threadIdx.x;
    const int b = idx >> 13;
    const int e2 = idx & 8191;
    const float dec = sigmoidf_(decay_ptr[0]);
    const float dS = exp2f((float)S_ * log2f(dec));

    const float2* G = (const float2*)(g_G + (size_t)b * NCH * C_ * C_) + e2;
    float2* M = (float2*)(g_M + (size_t)b * NCH * C_ * C_) + e2;

    float2 m = make_float2(0.f, 0.f);
    #pragma unroll
    for (int jb = 0; jb < NCH; jb += 8) {
        float2 buf[8];
        #pragma unroll
        for (int u = 0; u < 8; u++) buf[u] = G[(size_t)(jb + u) * 8192];
        #pragma unroll
        for (int u = 0; u < 8; u++) {
            M[(size_t)(jb + u) * 8192] = m;
            m.x = fmaf(dS, m.x, buf[u].x);
            m.y = fmaf(dS, m.y, buf[u].y);
        }
    }
}

// ---------------- 3c) retrieval per chunk + fused r2 = R @ oc, emit fp16 hi/lo ----------------
__global__ __launch_bounds__(256) void retr_kernel(const float* __restrict__ decay_ptr,
                                                   const float* __restrict__ oc) {
    const int j = blockIdx.x;
    const int b = blockIdx.y;
    const float dec = sigmoidf_(decay_ptr[0]);
    const float l2d = log2f(dec);

    __shared__ char buf[49152];
    float (*Qs)[64]  = (float(*)[64])(buf);
    float (*Ks2)[64] = (float(*)[64])(buf + 8192);
    float (*As)[64]  = (float(*)[64])(buf + 16384);
    float (*Vs)[128] = (float(*)[128])(buf + 32768);
    float* Rs = (float*)buf;

    const int tid = threadIdx.x;
    const float* base = g_qkv + ((size_t)b * T_ + (size_t)j * S_) * (3 * C_);

    {
        const int ti = tid >> 4;
        const int ts = tid & 15;
        const int li = tid >> 2;
        const int lp = tid & 3;

        float acc[4][4] = {};
        for (int c0 = 0; c0 < C_; c0 += 32) {
            #pragma unroll
            for (int u = 0; u < 2; u++) {
                int c = lp * 8 + u * 4;
                float4 qv = *(const float4*)(base + (size_t)li * (3 * C_) + c0 + c);
                Qs[c + 0][li] = qv.x; Qs[c + 1][li] = qv.y;
                Qs[c + 2][li] = qv.z; Qs[c + 3][li] = qv.w;
                float4 kv = *(const float4*)(base + (size_t)li * (3 * C_) + C_ + c0 + c);
                Ks2[c + 0][li] = kv.x; Ks2[c + 1][li] = kv.y;
                Ks2[c + 2][li] = kv.z; Ks2[c + 3][li] = kv.w;
            }
            __syncthreads();
            #pragma unroll
            for (int cc = 0; cc < 32; cc++) {
                float4 a4 = *(const float4*)&Qs[cc][ti * 4];
                float4 b4 = *(const float4*)&Ks2[cc][ts * 4];
                float ar[4] = {a4.x, a4.y, a4.z, a4.w};
                float br[4] = {b4.x, b4.y, b4.z, b4.w};
                #pragma unroll
                for (int m = 0; m < 4; m++)
                    #pragma unroll
                    for (int n = 0; n < 4; n++)
                        acc[m][n] = fmaf(ar[m], br[n], acc[m][n]);
            }
            __syncthreads();
        }
        #pragma unroll
        for (int m = 0; m < 4; m++) {
            const int i = ti * 4 + m;
            #pragma unroll
            for (int n = 0; n < 4; n++) {
                const int s = ts * 4 + n;
                float v = 0.f;
                if (s < i) v = acc[m][n] * exp2f((float)(i - 1 - s) * l2d);
                As[s][i] = v;
            }
        }
    }
    __syncthreads();

    const int ti2 = tid >> 4;
    const int td  = tid & 15;
    const int lr  = tid >> 3;
    const int lq  = tid & 7;

    float accA[4][8] = {};
    float accM[4][8] = {};

    for (int s0 = 0; s0 < S_; s0 += 32) {
        #pragma unroll
        for (int u = 0; u < 4; u++) {
            int c4 = lq + u * 8;
            *(float4*)&Vs[lr][c4 * 4] =
                *(const float4*)(base + (size_t)(s0 + lr) * (3 * C_) + 2 * C_ + c4 * 4);
        }
        __syncthreads();
        #pragma unroll
        for (int ss = 0; ss < 32; ss++) {
            float4 a4 = *(const float4*)&As[s0 + ss][ti2 * 4];
            float4 b0 = *(const float4*)&Vs[ss][td * 8];
            float4 b1 = *(const float4*)&Vs[ss][td * 8 + 4];
            float ar[4] = {a4.x, a4.y, a4.z, a4.w};
            float br[8] = {b0.x, b0.y, b0.z, b0.w, b1.x, b1.y, b1.z, b1.w};
            #pragma unroll
            for (int m = 0; m < 4; m++)
                #pragma unroll
                for (int n = 0; n < 8; n++)
                    accA[m][n] = fmaf(ar[m], br[n], accA[m][n]);
        }
        __syncthreads();
    }

    const float* Mbase = g_M + (size_t)(b * NCH + j) * C_ * C_;
    {
        const int li = tid >> 2;
        const int lp = tid & 3;
        for (int c0 = 0; c0 < C_; c0 += 32) {
            #pragma unroll
            for (int u = 0; u < 2; u++) {
                int c = lp * 8 + u * 4;
                float4 qv = *(const float4*)(base + (size_t)li * (3 * C_) + c0 + c);
                Qs[c + 0][li] = qv.x; Qs[c + 1][li] = qv.y;
                Qs[c + 2][li] = qv.z; Qs[c + 3][li] = qv.w;
            }
            #pragma unroll
            for (int u = 0; u < 4; u++) {
                int c4 = lq + u * 8;
                *(float4*)&Vs[lr][c4 * 4] =
                    *(const float4*)(Mbase + (size_t)(c0 + lr) * C_ + c4 * 4);
            }
            __syncthreads();
            #pragma unroll
            for (int cc = 0; cc < 32; cc++) {
                float4 a4 = *(const float4*)&Qs[cc][ti2 * 4];
                float4 b0 = *(const float4*)&Vs[cc][td * 8];
                float4 b1 = *(const float4*)&Vs[cc][td * 8 + 4];
                float ar[4] = {a4.x, a4.y, a4.z, a4.w};
                float br[8] = {b0.x, b0.y, b0.z, b0.w, b1.x, b1.y, b1.z, b1.w};
                #pragma unroll
                for (int m = 0; m < 4; m++)
                    #pragma unroll
                    for (int n = 0; n < 8; n++)
                        accM[m][n] = fmaf(ar[m], br[n], accM[m][n]);
            }
            __syncthreads();
        }
    }

    __syncthreads();
    #pragma unroll
    for (int m = 0; m < 4; m++) {
        const int i = ti2 * 4 + m;
        const float di = exp2f((float)i * l2d);
        #pragma unroll
        for (int n = 0; n < 8; n++)
            Rs[i * 132 + td * 8 + n] = fmaf(di, accM[m][n], accA[m][n]);
    }
    __syncthreads();

    {
        const int i0 = (tid >> 4) * 4;
        const int j0 = (tid & 15) * 4;
        float racc[4][4] = {};
        #pragma unroll 4
        for (int d4 = 0; d4 < 128; d4 += 4) {
            float4 a0 = *(const float4*)&Rs[(i0 + 0) * 132 + d4];
            float4 a1 = *(const float4*)&Rs[(i0 + 1) * 132 + d4];
            float4 a2 = *(const float4*)&Rs[(i0 + 2) * 132 + d4];
            float4 a3 = *(const float4*)&Rs[(i0 + 3) * 132 + d4];
            float am[4][4] = {{a0.x, a0.y, a0.z, a0.w},
                              {a1.x, a1.y, a1.z, a1.w},
                              {a2.x, a2.y, a2.z, a2.w},
                              {a3.x, a3.y, a3.z, a3.w}};
            #pragma unroll
            for (int dd = 0; dd < 4; dd++) {
                float4 bv = __ldg((const float4*)(oc + (size_t)(d4 + dd) * NB2 + j0));
                float br[4] = {bv.x, bv.y, bv.z, bv.w};
                #pragma unroll
                for (int ii = 0; ii < 4; ii++)
                    #pragma unroll
                    for (int jj = 0; jj < 4; jj++)
                        racc[ii][jj] = fmaf(am[ii][dd], br[jj], racc[ii][jj]);
            }
        }
        const size_t mbase = (size_t)b * T_ + (size_t)j * S_;
        #pragma unroll
        for (int ii = 0; ii < 4; ii++) {
            unsigned short h[4], l[4];
            #pragma unroll
            for (int jj = 0; jj < 4; jj++) {
                __half hb = __float2half_rn(racc[ii][jj]);
                __half lb = __float2half_rn(racc[ii][jj] - __half2float(hb));
                h[jj] = __half_as_ushort(hb);
                l[jj] = __half_as_ushort(lb);
            }
            const size_t o = (mbase + i0 + ii) * NB2 + j0;
            *(uint2*)(g_r2h + o) = make_uint2((uint32_t)h[0] | ((uint32_t)h[1] << 16),
                                              (uint32_t)h[2] | ((uint32_t)h[3] << 16));
            *(uint2*)(g_r2l + o) = make_uint2((uint32_t)l[0] | ((uint32_t)l[1] << 16),
                                              (uint32_t)l[2] | ((uint32_t)l[3] << 16));
        }
    }
}

// ---------------- 4) out = r2 @ basis^T * scale, fp16 2-term ----------------
#define OBUF 24576
__global__ __launch_bounds__(256) void out2_mma_kernel(float* __restrict__ Cout,
                                                       const float* __restrict__ scale_ptr) {
    extern __shared__ char sm[];
    const uint32_t sbase = smem_to_u32(sm);
    const int tid = threadIdx.x;
    const int warp = tid >> 5, lane = tid & 31;
    const int bm = blockIdx.y * 128;
    const int bn = blockIdx.x * 128;
    const int wm = (warp >> 2) * 64;
    const int wn = (warp & 3) * 32;

    const int frow = tid >> 2;
    const int fkq = tid & 3;

    const int arow = lane & 15;
    const int akg = lane >> 4;
    const int fA = (arow >> 1) & 3;
    const int brow = ((lane >> 4) & 1) * 8 + (lane & 7);
    const int bkg = (lane >> 3) & 1;
    const int fB = (brow >> 1) & 3;

    float acc[4][4][4] = {};

    auto fill = [&](int stage, int c0) {
        const uint32_t nb = sbase + stage * OBUF;
        #pragma unroll
        for (int it = 0; it < 2; it++) {
            const int row = frow + it * 64;
            const uint32_t dst = nb + row * 64 + ((fkq ^ ((row >> 1) & 3)) * 16);
            CP_ASYNC16(dst,         g_r2h + (size_t)(bm + row) * NB2 + c0 + fkq * 8);
            CP_ASYNC16(dst + 8192,  g_r2l + (size_t)(bm + row) * NB2 + c0 + fkq * 8);
            CP_ASYNC16(dst + 16384, g_bt + (size_t)(bn + row) * NB2 + c0 + fkq * 8);
        }
    };

    fill(0, 0);
    CP_COMMIT();

    for (int ch = 0; ch < 2; ch++) {
        if (ch + 1 < 2) { fill(ch + 1, 32); CP_COMMIT(); }
        if (ch == 0) { CP_WAIT1(); } else { CP_WAIT0(); }
        __syncthreads();

        const uint32_t cb = sbase + ch * OBUF;
        #pragma unroll
        for (int ks = 0; ks < 2; ks++) {
            uint32_t a_h[4][4], a_l[4][4];
            const uint32_t achunk = (uint32_t)(((ks * 2 + akg) ^ fA) * 16);
            #pragma unroll
            for (int mi = 0; mi < 4; mi++) {
                const uint32_t aaddr = cb + (uint32_t)((wm + mi * 16 + arow) * 64) + achunk;
                ldsm_x4(a_h[mi], aaddr);
                ldsm_x4(a_l[mi], aaddr + 8192);
            }
            uint32_t b_f[4][2];
            const uint32_t bchunk = (uint32_t)(((ks * 2 + bkg) ^ fB) * 16);
            #pragma unroll
            for (int nip = 0; nip < 2; nip++) {
                const uint32_t baddr = cb + 16384 +
                    (uint32_t)((wn + nip * 16 + brow) * 64) + bchunk;
                uint32_t rh[4];
                ldsm_x4(rh, baddr);
                b_f[nip * 2 + 0][0] = rh[0]; b_f[nip * 2 + 0][1] = rh[1];
                b_f[nip * 2 + 1][0] = rh[2]; b_f[nip * 2 + 1][1] = rh[3];
            }
            #pragma unroll
            for (int mi = 0; mi < 4; mi++)
                #pragma unroll
                for (int ni = 0; ni < 4; ni++) {
                    mma_f16(acc[mi][ni], a_l[mi], b_f[ni]);
                    mma_f16(acc[mi][ni], a_h[mi], b_f[ni]);
                }
        }
        __syncthreads();
    }

    const float sc = *scale_ptr;
    const int g = lane >> 2, tg = lane & 3;
    #pragma unroll
    for (int mi = 0; mi < 4; mi++) {
        const int r0 = bm + wm + mi * 16 + g;
        #pragma unroll
        for (int ni = 0; ni < 4; ni++) {
            const int col = bn + wn + ni * 8 + tg * 2;
            *(float2*)(Cout + (size_t)r0 * V_ + col) =
                make_float2(acc[mi][ni][0] * sc, acc[mi][ni][1] * sc);
            *(float2*)(Cout + (size_t)(r0 + 8) * V_ + col) =
                make_float2(acc[mi][ni][2] * sc, acc[mi][ni][3] * sc);
        }
    }
}

// ---------------- launch ----------------
extern "C" void kernel_launch(void* const* d_in, const int* in_sizes, int n_in,
                              void* d_out, int out_size) {
    const float* x      = (const float*)d_in[0];
    const float* basis  = (const float*)d_in[1];
    const float* qc     = (const float*)d_in[2];
    const float* kc     = (const float*)d_in[3];
    const float* vc     = (const float*)d_in[4];
    const float* oc     = (const float*)d_in[5];
    const float* decay  = (const float*)d_in[6];
    const float* oscale = (const float*)d_in[7];
    float* out = (float*)d_out;

    cudaFuncSetAttribute(qkv_mma_kernel, cudaFuncAttributeMaxDynamicSharedMemorySize, 3 * QKVBUF);
    cudaFuncSetAttribute(out2_mma_kernel, cudaFuncAttributeMaxDynamicSharedMemorySize, 2 * OBUF);

    cvt_x_kernel<<<(MT * V_) / 1024, 256>>>(x);
    cvt_basis_kernel<<<(V_ * NB2) / 1024, 256>>>(basis);
    logits_kernel<<<dim3(3, 8), 256>>>(basis, qc, kc, vc);
    softmax_w_kernel<<<3 * C_, 256>>>();
    qkv_mma_kernel<<<dim3(3, MT / 128), 256, 3 * QKVBUF>>>();
    chunk_g_kernel<<<dim3(NCH, B_), 256>>>(decay);
    scan_kernel<<<256, 256>>>(decay);
    retr_kernel<<<dim3(NCH, B_), 256>>>(decay, oc);
    out2_mma_kernel<<<dim3(V_ / 128, MT / 128), 256, 2 * OBUF>>>(out, oscale);
}

// round 15
// speedup vs baseline: 1.4537x; 1.1956x over previous
#include <cuda_runtime.h>
#include <cuda_fp16.h>
#include <math.h>
#include <stdint.h>

#define B_ 8
#define T_ 2048
#define V_ 1024
#define C_ 128
#define NB2 64   // 2*NB
#define S_ 64    // chunk size
#define NCH 32   // T_/S_
#define MT (B_ * T_)   // 16384

// ---------------- device scratch ----------------
__device__ unsigned short g_x16[(size_t)MT * V_];    // x fp16 (single), row-major [M][K]
__device__ unsigned short g_wt[3 * C_ * V_];         // W^T fp16 (single), [N][K]
__device__ float g_logits[3 * C_ * V_];              // logits [N][V]
__device__ unsigned short g_bt[V_ * NB2];            // basis fp16 (single) [N][K]
__device__ unsigned short g_r2h[(size_t)MT * NB2];   // r2 hi fp16 [M][64]
__device__ unsigned short g_r2l[(size_t)MT * NB2];   // r2 lo fp16
__device__ float g_qkv[(size_t)MT * 3 * C_];         // (B*T, 384)
__device__ float g_G[B_ * NCH * C_ * C_];            // per-chunk outer-product sums
__device__ float g_M[B_ * NCH * C_ * C_];            // chunk-boundary states

__device__ __forceinline__ float sigmoidf_(float x) { return 1.0f / (1.0f + expf(-x)); }

__device__ __forceinline__ void mma_f16(float* c, const uint32_t* a, const uint32_t* b) {
    asm volatile(
        "mma.sync.aligned.m16n8k16.row.col.f32.f16.f16.f32 "
        "{%0,%1,%2,%3}, {%4,%5,%6,%7}, {%8,%9}, {%0,%1,%2,%3};"
        : "+f"(c[0]), "+f"(c[1]), "+f"(c[2]), "+f"(c[3])
        : "r"(a[0]), "r"(a[1]), "r"(a[2]), "r"(a[3]), "r"(b[0]), "r"(b[1]));
}

__device__ __forceinline__ uint32_t smem_to_u32(const void* p) {
    uint32_t a;
    asm("{ .reg .u64 t; cvta.to.shared.u64 t, %1; cvt.u32.u64 %0, t; }" : "=r"(a) : "l"(p));
    return a;
}

__device__ __forceinline__ void ldsm_x4(uint32_t* r, uint32_t addr) {
    asm volatile("ldmatrix.sync.aligned.m8n8.x4.shared.b16 {%0,%1,%2,%3}, [%4];"
                 : "=r"(r[0]), "=r"(r[1]), "=r"(r[2]), "=r"(r[3]) : "r"(addr));
}

#define CP_ASYNC16(dst, src) \
    asm volatile("cp.async.cg.shared.global [%0], [%1], 16;" :: "r"(dst), "l"(src))
#define CP_COMMIT() asm volatile("cp.async.commit_group;" ::: "memory")
#define CP_WAIT0()  asm volatile("cp.async.wait_group 0;" ::: "memory")
#define CP_WAIT1()  asm volatile("cp.async.wait_group 1;" ::: "memory")

// ---------------- 0a) convert x to fp16 (single), row-major [M][K] ----------------
__global__ __launch_bounds__(256) void cvt_x_kernel(const float* __restrict__ x) {
    const size_t i = ((size_t)blockIdx.x * 256 + threadIdx.x) * 4;
    float4 v = *(const float4*)(x + i);
    float vv[4] = {v.x, v.y, v.z, v.w};
    unsigned short h[4];
    #pragma unroll
    for (int u = 0; u < 4; u++) h[u] = __half_as_ushort(__float2half_rn(vv[u]));
    *(uint2*)(g_x16 + i) = make_uint2((uint32_t)h[0] | ((uint32_t)h[1] << 16),
                                      (uint32_t)h[2] | ((uint32_t)h[3] << 16));
}

// ---------------- 0b) convert basis to fp16 [N][K] ----------------
__global__ __launch_bounds__(256) void cvt_basis_kernel(const float* __restrict__ basis) {
    const size_t i = ((size_t)blockIdx.x * 256 + threadIdx.x) * 4;
    float4 v = *(const float4*)(basis + i);
    float vv[4] = {v.x, v.y, v.z, v.w};
    unsigned short h[4];
    #pragma unroll
    for (int u = 0; u < 4; u++) h[u] = __half_as_ushort(__float2half_rn(vv[u]));
    *(uint2*)(g_bt + i) = make_uint2((uint32_t)h[0] | ((uint32_t)h[1] << 16),
                                     (uint32_t)h[2] | ((uint32_t)h[3] << 16));
}

// ---------------- 1a) logits = coeffs @ basis^T, written [N][V] ----------------
__global__ __launch_bounds__(256) void logits_kernel(const float* __restrict__ basis,
                                                     const float* __restrict__ qc,
                                                     const float* __restrict__ kc,
                                                     const float* __restrict__ vc) {
    const int w = blockIdx.x;
    const int vb = blockIdx.y;
    const float* coef = (w == 0 ? qc : (w == 1 ? kc : vc));

    __shared__ float Cs[NB2][C_ + 4];
    __shared__ float Bs[NB2][C_ + 4];

    const int tid = threadIdx.x;
    const int lr = tid >> 1;
    const int lk = (tid & 1) * 32;

    #pragma unroll
    for (int u = 0; u < 8; u++) {
        const int k = lk + u * 4;
        float4 cv = *(const float4*)(coef + (size_t)lr * NB2 + k);
        Cs[k + 0][lr] = cv.x; Cs[k + 1][lr] = cv.y;
        Cs[k + 2][lr] = cv.z; Cs[k + 3][lr] = cv.w;
        float4 bv = *(const float4*)(basis + (size_t)(vb * 128 + lr) * NB2 + k);
        Bs[k + 0][lr] = bv.x; Bs[k + 1][lr] = bv.y;
        Bs[k + 2][lr] = bv.z; Bs[k + 3][lr] = bv.w;
    }
    __syncthreads();

    const int trow = tid >> 4;
    const int tcol = tid & 15;
    float acc[8][8] = {};
    #pragma unroll
    for (int kk = 0; kk < NB2; kk++) {
        float ar[8], br[8];
        *(float4*)&ar[0] = *(const float4*)&Cs[kk][trow * 8];
        *(float4*)&ar[4] = *(const float4*)&Cs[kk][trow * 8 + 4];
        *(float4*)&br[0] = *(const float4*)&Bs[kk][tcol * 8];
        *(float4*)&br[4] = *(const float4*)&Bs[kk][tcol * 8 + 4];
        #pragma unroll
        for (int i = 0; i < 8; i++)
            #pragma unroll
            for (int jn = 0; jn < 8; jn++)
                acc[i][jn] = fmaf(ar[i], br[jn], acc[i][jn]);
    }
    #pragma unroll
    for (int i = 0; i < 8; i++) {
        float* lrow = g_logits + (size_t)(w * C_ + trow * 8 + i) * V_ + vb * 128 + tcol * 8;
        *(float4*)(lrow)     = make_float4(acc[i][0], acc[i][1], acc[i][2], acc[i][3]);
        *(float4*)(lrow + 4) = make_float4(acc[i][4], acc[i][5], acc[i][6], acc[i][7]);
    }
}

// ---------------- 1b) column softmax over V, emit fp16 [N][K] ----------------
__global__ __launch_bounds__(256) void softmax_w_kernel() {
    const int n = blockIdx.x;
    const int tid = threadIdx.x;
    __shared__ float red[8];
    __shared__ float sval;

    float4 s4 = *(const float4*)(g_logits + (size_t)n * V_ + tid * 4);
    float s[4] = {s4.x, s4.y, s4.z, s4.w};

    float m = fmaxf(fmaxf(s[0], s[1]), fmaxf(s[2], s[3]));
    #pragma unroll
    for (int o = 16; o; o >>= 1) m = fmaxf(m, __shfl_xor_sync(0xffffffffu, m, o));
    if ((tid & 31) == 0) red[tid >> 5] = m;
    __syncthreads();
    if (tid < 8) {
        float t = red[tid];
        #pragma unroll
        for (int o = 4; o; o >>= 1) t = fmaxf(t, __shfl_xor_sync(0xffu, t, o));
        if (tid == 0) sval = t;
    }
    __syncthreads();
    const float M = sval;

    float e[4];
    float su = 0.f;
    #pragma unroll
    for (int u = 0; u < 4; u++) { e[u] = expf(s[u] - M); su += e[u]; }
    #pragma unroll
    for (int o = 16; o; o >>= 1) su += __shfl_xor_sync(0xffffffffu, su, o);
    if ((tid & 31) == 0) red[tid >> 5] = su;
    __syncthreads();
    if (tid < 8) {
        float t = red[tid];
        #pragma unroll
        for (int o = 4; o; o >>= 1) t += __shfl_xor_sync(0xffu, t, o);
        if (tid == 0) sval = t;
    }
    __syncthreads();
    const float inv = 1.0f / sval;

    unsigned short h[4];
    #pragma unroll
    for (int u = 0; u < 4; u++)
        h[u] = __half_as_ushort(__float2half_rn(e[u] * inv));
    *(uint2*)(g_wt + (size_t)n * V_ + tid * 4) =
        make_uint2((uint32_t)h[0] | ((uint32_t)h[1] << 16),
                   (uint32_t)h[2] | ((uint32_t)h[3] << 16));
}

// ---------------- 2) QKV GEMM: fp16 single-term mma.sync + ldmatrix + 3-stage cp.async ----------------
// BM=128, BN=128, 256 threads, warp tile 64x32. Stage: A 8K | B 8K = 16 KB.
#define QKVBUF 16384
__global__ __launch_bounds__(256) void qkv_mma_kernel() {
    extern __shared__ char sm[];
    const uint32_t sbase = smem_to_u32(sm);
    const int tid = threadIdx.x;
    const int warp = tid >> 5, lane = tid & 31;
    const int bm = blockIdx.y * 128;
    const int bn = blockIdx.x * 128;
    const int wm = (warp >> 2) * 64;
    const int wn = (warp & 3) * 32;

    const int frow = tid >> 2;
    const int fkq = tid & 3;

    const int arow = lane & 15;
    const int akg = lane >> 4;
    const int fA = (arow >> 1) & 3;
    const int brow = ((lane >> 4) & 1) * 8 + (lane & 7);
    const int bkg = (lane >> 3) & 1;
    const int fB = (brow >> 1) & 3;

    float acc[4][4][4] = {};

    auto fill = [&](int stage, int c0) {
        const uint32_t nb = sbase + stage * QKVBUF;
        #pragma unroll
        for (int it = 0; it < 2; it++) {
            const int row = frow + it * 64;
            const uint32_t dst = nb + row * 64 + ((fkq ^ ((row >> 1) & 3)) * 16);
            CP_ASYNC16(dst,        g_x16 + (size_t)(bm + row) * V_ + c0 + fkq * 8);
            CP_ASYNC16(dst + 8192, g_wt + (size_t)(bn + row) * V_ + c0 + fkq * 8);
        }
    };

    fill(0, 0);  CP_COMMIT();
    fill(1, 32); CP_COMMIT();

    for (int ch = 0; ch < 32; ch++) {
        CP_WAIT1();
        __syncthreads();

        const uint32_t cb = sbase + (ch % 3) * QKVBUF;
        #pragma unroll
        for (int ks = 0; ks < 2; ks++) {
            uint32_t a_f[4][4];
            const uint32_t achunk = (uint32_t)(((ks * 2 + akg) ^ fA) * 16);
            #pragma unroll
            for (int mi = 0; mi < 4; mi++) {
                const uint32_t aaddr = cb + (uint32_t)((wm + mi * 16 + arow) * 64) + achunk;
                ldsm_x4(a_f[mi], aaddr);
            }
            uint32_t b_f[4][2];
            const uint32_t bchunk = (uint32_t)(((ks * 2 + bkg) ^ fB) * 16);
            #pragma unroll
            for (int nip = 0; nip < 2; nip++) {
                const uint32_t baddr = cb + 8192 +
                    (uint32_t)((wn + nip * 16 + brow) * 64) + bchunk;
                uint32_t rh[4];
                ldsm_x4(rh, baddr);
                b_f[nip * 2 + 0][0] = rh[0]; b_f[nip * 2 + 0][1] = rh[1];
                b_f[nip * 2 + 1][0] = rh[2]; b_f[nip * 2 + 1][1] = rh[3];
            }
            #pragma unroll
            for (int mi = 0; mi < 4; mi++)
                #pragma unroll
                for (int ni = 0; ni < 4; ni++)
                    mma_f16(acc[mi][ni], a_f[mi], b_f[ni]);
        }

        __syncthreads();
        if (ch + 2 < 32) fill((ch + 2) % 3, (ch + 2) * 32);
        CP_COMMIT();
    }

    const int g = lane >> 2, tg = lane & 3;
    #pragma unroll
    for (int mi = 0; mi < 4; mi++) {
        const int r0 = bm + wm + mi * 16 + g;
        #pragma unroll
        for (int ni = 0; ni < 4; ni++) {
            const int col = bn + wn + ni * 8 + tg * 2;
            *(float2*)(g_qkv + (size_t)r0 * (3 * C_) + col) =
                make_float2(acc[mi][ni][0], acc[mi][ni][1]);
            *(float2*)(g_qkv + (size_t)(r0 + 8) * (3 * C_) + col) =
                make_float2(acc[mi][ni][2], acc[mi][ni][3]);
        }
    }
}

// ---------------- 3a) per-chunk outer-product sums, merged 128x128 ----------------
__global__ __launch_bounds__(256) void chunk_g_kernel(const float* __restrict__ decay_ptr) {
    const int j = blockIdx.x;
    const int b = blockIdx.y;
    const float dec = sigmoidf_(decay_ptr[0]);
    const float l2d = log2f(dec);

    __shared__ float Ks[32][128];
    __shared__ float Vs[32][128];

    const int tid = threadIdx.x;
    const int trow = tid >> 4;
    const int tcol = tid & 15;
    const int r = tid >> 3;
    const int q8 = tid & 7;

    float acc[8][8] = {};
    const float* base = g_qkv + ((size_t)b * T_ + (size_t)j * S_) * (3 * C_);

    #pragma unroll
    for (int i0 = 0; i0 < S_; i0 += 32) {
        const float sc = exp2f((float)(S_ - 1 - (i0 + r)) * l2d);
        const float* row = base + (size_t)(i0 + r) * (3 * C_);
        #pragma unroll
        for (int u = 0; u < 4; u++) {
            const int c4 = (q8 + u * 8) * 4;
            float4 kv = *(const float4*)(row + C_ + c4);
            Ks[r][c4 + 0] = kv.x * sc;
            Ks[r][c4 + 1] = kv.y * sc;
            Ks[r][c4 + 2] = kv.z * sc;
            Ks[r][c4 + 3] = kv.w * sc;
            *(float4*)&Vs[r][c4] = *(const float4*)(row + 2 * C_ + c4);
        }
        __syncthreads();
        #pragma unroll
        for (int ii = 0; ii < 32; ii++) {
            float ar[8], br[8];
            *(float4*)&ar[0] = *(const float4*)&Ks[ii][trow * 8];
            *(float4*)&ar[4] = *(const float4*)&Ks[ii][trow * 8 + 4];
            *(float4*)&br[0] = *(const float4*)&Vs[ii][tcol * 8];
            *(float4*)&br[4] = *(const float4*)&Vs[ii][tcol * 8 + 4];
            #pragma unroll
            for (int m = 0; m < 8; m++)
                #pragma unroll
                for (int n = 0; n < 8; n++)
                    acc[m][n] = fmaf(ar[m], br[n], acc[m][n]);
        }
        __syncthreads();
    }

    float* gout = g_G + ((size_t)(b * NCH + j) * C_ * C_);
    #pragma unroll
    for (int m = 0; m < 8; m++) {
        float* grow = gout + (size_t)(trow * 8 + m) * C_ + tcol * 8;
        *(float4*)(grow)     = make_float4(acc[m][0], acc[m][1], acc[m][2], acc[m][3]);
        *(float4*)(grow + 4) = make_float4(acc[m][4], acc[m][5], acc[m][6], acc[m][7]);
    }
}

// ---------------- 3b) scan, float2 per thread ----------------
__global__ void scan_kernel(const float* __restrict__ decay_ptr) {
    const int idx = blockIdx.x * blockDim.x + threadIdx.x;
    const int b = idx >> 13;
    const int e2 = idx & 8191;
    const float dec = sigmoidf_(decay_ptr[0]);
    const float dS = exp2f((float)S_ * log2f(dec));

    const float2* G = (const float2*)(g_G + (size_t)b * NCH * C_ * C_) + e2;
    float2* M = (float2*)(g_M + (size_t)b * NCH * C_ * C_) + e2;

    float2 m = make_float2(0.f, 0.f);
    #pragma unroll
    for (int jb = 0; jb < NCH; jb += 8) {
        float2 buf[8];
        #pragma unroll
        for (int u = 0; u < 8; u++) buf[u] = G[(size_t)(jb + u) * 8192];
        #pragma unroll
        for (int u = 0; u < 8; u++) {
            M[(size_t)(jb + u) * 8192] = m;
            m.x = fmaf(dS, m.x, buf[u].x);
            m.y = fmaf(dS, m.y, buf[u].y);
        }
    }
}

// ---------------- 3c) retrieval per chunk + fused r2 = R @ oc, emit fp16 hi/lo ----------------
__global__ __launch_bounds__(256) void retr_kernel(const float* __restrict__ decay_ptr,
                                                   const float* __restrict__ oc) {
    const int j = blockIdx.x;
    const int b = blockIdx.y;
    const float dec = sigmoidf_(decay_ptr[0]);
    const float l2d = log2f(dec);

    __shared__ char buf[49152];
    float (*Qs)[64]  = (float(*)[64])(buf);
    float (*Ks2)[64] = (float(*)[64])(buf + 8192);
    float (*As)[64]  = (float(*)[64])(buf + 16384);
    float (*Vs)[128] = (float(*)[128])(buf + 32768);
    float* Rs = (float*)buf;

    const int tid = threadIdx.x;
    const float* base = g_qkv + ((size_t)b * T_ + (size_t)j * S_) * (3 * C_);

    {
        const int ti = tid >> 4;
        const int ts = tid & 15;
        const int li = tid >> 2;
        const int lp = tid & 3;

        float acc[4][4] = {};
        for (int c0 = 0; c0 < C_; c0 += 32) {
            #pragma unroll
            for (int u = 0; u < 2; u++) {
                int c = lp * 8 + u * 4;
                float4 qv = *(const float4*)(base + (size_t)li * (3 * C_) + c0 + c);
                Qs[c + 0][li] = qv.x; Qs[c + 1][li] = qv.y;
                Qs[c + 2][li] = qv.z; Qs[c + 3][li] = qv.w;
                float4 kv = *(const float4*)(base + (size_t)li * (3 * C_) + C_ + c0 + c);
                Ks2[c + 0][li] = kv.x; Ks2[c + 1][li] = kv.y;
                Ks2[c + 2][li] = kv.z; Ks2[c + 3][li] = kv.w;
            }
            __syncthreads();
            #pragma unroll
            for (int cc = 0; cc < 32; cc++) {
                float4 a4 = *(const float4*)&Qs[cc][ti * 4];
                float4 b4 = *(const float4*)&Ks2[cc][ts * 4];
                float ar[4] = {a4.x, a4.y, a4.z, a4.w};
                float br[4] = {b4.x, b4.y, b4.z, b4.w};
                #pragma unroll
                for (int m = 0; m < 4; m++)
                    #pragma unroll
                    for (int n = 0; n < 4; n++)
                        acc[m][n] = fmaf(ar[m], br[n], acc[m][n]);
            }
            __syncthreads();
        }
        #pragma unroll
        for (int m = 0; m < 4; m++) {
            const int i = ti * 4 + m;
            #pragma unroll
            for (int n = 0; n < 4; n++) {
                const int s = ts * 4 + n;
                float v = 0.f;
                if (s < i) v = acc[m][n] * exp2f((float)(i - 1 - s) * l2d);
                As[s][i] = v;
            }
        }
    }
    __syncthreads();

    const int ti2 = tid >> 4;
    const int td  = tid & 15;
    const int lr  = tid >> 3;
    const int lq  = tid & 7;

    float accA[4][8] = {};
    float accM[4][8] = {};

    for (int s0 = 0; s0 < S_; s0 += 32) {
        #pragma unroll
        for (int u = 0; u < 4; u++) {
            int c4 = lq + u * 8;
            *(float4*)&Vs[lr][c4 * 4] =
                *(const float4*)(base + (size_t)(s0 + lr) * (3 * C_) + 2 * C_ + c4 * 4);
        }
        __syncthreads();
        #pragma unroll
        for (int ss = 0; ss < 32; ss++) {
            float4 a4 = *(const float4*)&As[s0 + ss][ti2 * 4];
            float4 b0 = *(const float4*)&Vs[ss][td * 8];
            float4 b1 = *(const float4*)&Vs[ss][td * 8 + 4];
            float ar[4] = {a4.x, a4.y, a4.z, a4.w};
            float br[8] = {b0.x, b0.y, b0.z, b0.w, b1.x, b1.y, b1.z, b1.w};
            #pragma unroll
            for (int m = 0; m < 4; m++)
                #pragma unroll
                for (int n = 0; n < 8; n++)
                    accA[m][n] = fmaf(ar[m], br[n], accA[m][n]);
        }
        __syncthreads();
    }

    const float* Mbase = g_M + (size_t)(b * NCH + j) * C_ * C_;
    {
        const int li = tid >> 2;
        const int lp = tid & 3;
        for (int c0 = 0; c0 < C_; c0 += 32) {
            #pragma unroll
            for (int u = 0; u < 2; u++) {
                int c = lp * 8 + u * 4;
                float4 qv = *(const float4*)(base + (size_t)li * (3 * C_) + c0 + c);
                Qs[c + 0][li] = qv.x; Qs[c + 1][li] = qv.y;
                Qs[c + 2][li] = qv.z; Qs[c + 3][li] = qv.w;
            }
            #pragma unroll
            for (int u = 0; u < 4; u++) {
                int c4 = lq + u * 8;
                *(float4*)&Vs[lr][c4 * 4] =
                    *(const float4*)(Mbase + (size_t)(c0 + lr) * C_ + c4 * 4);
            }
            __syncthreads();
            #pragma unroll
            for (int cc = 0; cc < 32; cc++) {
                float4 a4 = *(const float4*)&Qs[cc][ti2 * 4];
                float4 b0 = *(const float4*)&Vs[cc][td * 8];
                float4 b1 = *(const float4*)&Vs[cc][td * 8 + 4];
                float ar[4] = {a4.x, a4.y, a4.z, a4.w};
                float br[8] = {b0.x, b0.y, b0.z, b0.w, b1.x, b1.y, b1.z, b1.w};
                #pragma unroll
                for (int m = 0; m < 4; m++)
                    #pragma unroll
                    for (int n = 0; n < 8; n++)
                        accM[m][n] = fmaf(ar[m], br[n], accM[m][n]);
            }
            __syncthreads();
        }
    }

    __syncthreads();
    #pragma unroll
    for (int m = 0; m < 4; m++) {
        const int i = ti2 * 4 + m;
        const float di = exp2f((float)i * l2d);
        #pragma unroll
        for (int n = 0; n < 8; n++)
            Rs[i * 132 + td * 8 + n] = fmaf(di, accM[m][n], accA[m][n]);
    }
    __syncthreads();

    {
        const int i0 = (tid >> 4) * 4;
        const int j0 = (tid & 15) * 4;
        float racc[4][4] = {};
        #pragma unroll 4
        for (int d4 = 0; d4 < 128; d4 += 4) {
            float4 a0 = *(const float4*)&Rs[(i0 + 0) * 132 + d4];
            float4 a1 = *(const float4*)&Rs[(i0 + 1) * 132 + d4];
            float4 a2 = *(const float4*)&Rs[(i0 + 2) * 132 + d4];
            float4 a3 = *(const float4*)&Rs[(i0 + 3) * 132 + d4];
            float am[4][4] = {{a0.x, a0.y, a0.z, a0.w},
                              {a1.x, a1.y, a1.z, a1.w},
                              {a2.x, a2.y, a2.z, a2.w},
                              {a3.x, a3.y, a3.z, a3.w}};
            #pragma unroll
            for (int dd = 0; dd < 4; dd++) {
                float4 bv = __ldg((const float4*)(oc + (size_t)(d4 + dd) * NB2 + j0));
                float br[4] = {bv.x, bv.y, bv.z, bv.w};
                #pragma unroll
                for (int ii = 0; ii < 4; ii++)
                    #pragma unroll
                    for (int jj = 0; jj < 4; jj++)
                        racc[ii][jj] = fmaf(am[ii][dd], br[jj], racc[ii][jj]);
            }
        }
        const size_t mbase = (size_t)b * T_ + (size_t)j * S_;
        #pragma unroll
        for (int ii = 0; ii < 4; ii++) {
            unsigned short h[4], l[4];
            #pragma unroll
            for (int jj = 0; jj < 4; jj++) {
                __half hb = __float2half_rn(racc[ii][jj]);
                __half lb = __float2half_rn(racc[ii][jj] - __half2float(hb));
                h[jj] = __half_as_ushort(hb);
                l[jj] = __half_as_ushort(lb);
            }
            const size_t o = (mbase + i0 + ii) * NB2 + j0;
            *(uint2*)(g_r2h + o) = make_uint2((uint32_t)h[0] | ((uint32_t)h[1] << 16),
                                              (uint32_t)h[2] | ((uint32_t)h[3] << 16));
            *(uint2*)(g_r2l + o) = make_uint2((uint32_t)l[0] | ((uint32_t)l[1] << 16),
                                              (uint32_t)l[2] | ((uint32_t)l[3] << 16));
        }
    }
}

// ---------------- 4) out = r2 @ basis^T * scale, fp16 2-term ----------------
#define OBUF 24576
__global__ __launch_bounds__(256) void out2_mma_kernel(float* __restrict__ Cout,
                                                       const float* __restrict__ scale_ptr) {
    extern __shared__ char sm[];
    const uint32_t sbase = smem_to_u32(sm);
    const int tid = threadIdx.x;
    const int warp = tid >> 5, lane = tid & 31;
    const int bm = blockIdx.y * 128;
    const int bn = blockIdx.x * 128;
    const int wm = (warp >> 2) * 64;
    const int wn = (warp & 3) * 32;

    const int frow = tid >> 2;
    const int fkq = tid & 3;

    const int arow = lane & 15;
    const int akg = lane >> 4;
    const int fA = (arow >> 1) & 3;
    const int brow = ((lane >> 4) & 1) * 8 + (lane & 7);
    const int bkg = (lane >> 3) & 1;
    const int fB = (brow >> 1) & 3;

    float acc[4][4][4] = {};

    auto fill = [&](int stage, int c0) {
        const uint32_t nb = sbase + stage * OBUF;
        #pragma unroll
        for (int it = 0; it < 2; it++) {
            const int row = frow + it * 64;
            const uint32_t dst = nb + row * 64 + ((fkq ^ ((row >> 1) & 3)) * 16);
            CP_ASYNC16(dst,         g_r2h + (size_t)(bm + row) * NB2 + c0 + fkq * 8);
            CP_ASYNC16(dst + 8192,  g_r2l + (size_t)(bm + row) * NB2 + c0 + fkq * 8);
            CP_ASYNC16(dst + 16384, g_bt + (size_t)(bn + row) * NB2 + c0 + fkq * 8);
        }
    };

    fill(0, 0);
    CP_COMMIT();

    for (int ch = 0; ch < 2; ch++) {
        if (ch + 1 < 2) { fill(ch + 1, 32); CP_COMMIT(); }
        if (ch == 0) { CP_WAIT1(); } else { CP_WAIT0(); }
        __syncthreads();

        const uint32_t cb = sbase + ch * OBUF;
        #pragma unroll
        for (int ks = 0; ks < 2; ks++) {
            uint32_t a_h[4][4], a_l[4][4];
            const uint32_t achunk = (uint32_t)(((ks * 2 + akg) ^ fA) * 16);
            #pragma unroll
            for (int mi = 0; mi < 4; mi++) {
                const uint32_t aaddr = cb + (uint32_t)((wm + mi * 16 + arow) * 64) + achunk;
                ldsm_x4(a_h[mi], aaddr);
                ldsm_x4(a_l[mi], aaddr + 8192);
            }
            uint32_t b_f[4][2];
            const uint32_t bchunk = (uint32_t)(((ks * 2 + bkg) ^ fB) * 16);
            #pragma unroll
            for (int nip = 0; nip < 2; nip++) {
                const uint32_t baddr = cb + 16384 +
                    (uint32_t)((wn + nip * 16 + brow) * 64) + bchunk;
                uint32_t rh[4];
                ldsm_x4(rh, baddr);
                b_f[nip * 2 + 0][0] = rh[0]; b_f[nip * 2 + 0][1] = rh[1];
                b_f[nip * 2 + 1][0] = rh[2]; b_f[nip * 2 + 1][1] = rh[3];
            }
            #pragma unroll
            for (int mi = 0; mi < 4; mi++)
                #pragma unroll
                for (int ni = 0; ni < 4; ni++) {
                    mma_f16(acc[mi][ni], a_l[mi], b_f[ni]);
                    mma_f16(acc[mi][ni], a_h[mi], b_f[ni]);
                }
        }
        __syncthreads();
    }

    const float sc = *scale_ptr;
    const int g = lane >> 2, tg = lane & 3;
    #pragma unroll
    for (int mi = 0; mi < 4; mi++) {
        const int r0 = bm + wm + mi * 16 + g;
        #pragma unroll
        for (int ni = 0; ni < 4; ni++) {
            const int col = bn + wn + ni * 8 + tg * 2;
            *(float2*)(Cout + (size_t)r0 * V_ + col) =
                make_float2(acc[mi][ni][0] * sc, acc[mi][ni][1] * sc);
            *(float2*)(Cout + (size_t)(r0 + 8) * V_ + col) =
                make_float2(acc[mi][ni][2] * sc, acc[mi][ni][3] * sc);
        }
    }
}

// ---------------- launch ----------------
extern "C" void kernel_launch(void* const* d_in, const int* in_sizes, int n_in,
                              void* d_out, int out_size) {
    const float* x      = (const float*)d_in[0];
    const float* basis  = (const float*)d_in[1];
    const float* qc     = (const float*)d_in[2];
    const float* kc     = (const float*)d_in[3];
    const float* vc     = (const float*)d_in[4];
    const float* oc     = (const float*)d_in[5];
    const float* decay  = (const float*)d_in[6];
    const float* oscale = (const float*)d_in[7];
    float* out = (float*)d_out;

    cudaFuncSetAttribute(qkv_mma_kernel, cudaFuncAttributeMaxDynamicSharedMemorySize, 3 * QKVBUF);
    cudaFuncSetAttribute(out2_mma_kernel, cudaFuncAttributeMaxDynamicSharedMemorySize, 2 * OBUF);

    cvt_x_kernel<<<(MT * V_) / 1024, 256>>>(x);
    cvt_basis_kernel<<<(V_ * NB2) / 1024, 256>>>(basis);
    logits_kernel<<<dim3(3, 8), 256>>>(basis, qc, kc, vc);
    softmax_w_kernel<<<3 * C_, 256>>>();
    qkv_mma_kernel<<<dim3(3, MT / 128), 256, 3 * QKVBUF>>>();
    chunk_g_kernel<<<dim3(NCH, B_), 256>>>(decay);
    scan_kernel<<<256, 256>>>(decay);
    retr_kernel<<<dim3(NCH, B_), 256>>>(decay, oc);
    out2_mma_kernel<<<dim3(V_ / 128, MT / 128), 256, 2 * OBUF>>>(out, oscale);
}

// round 16
// speedup vs baseline: 1.6958x; 1.1665x over previous
#include <cuda_runtime.h>
#include <cuda_fp16.h>
#include <math.h>
#include <stdint.h>

#define B_ 8
#define T_ 2048
#define V_ 1024
#define C_ 128
#define NB2 64   // 2*NB
#define S_ 64    // chunk size
#define NCH 32   // T_/S_
#define MT (B_ * T_)   // 16384

// ---------------- device scratch ----------------
__device__ unsigned short g_x16[(size_t)MT * V_];    // x fp16 (single), row-major [M][K]
__device__ unsigned short g_wt[3 * C_ * V_];         // W^T fp16 (single), [N][K]
__device__ float g_logits[3 * C_ * V_];              // logits [N][V]
__device__ unsigned short g_bt[V_ * NB2];            // basis fp16 (single) [N][K]
__device__ unsigned short g_r2h[(size_t)MT * NB2];   // r2 hi fp16 [M][64]
__device__ unsigned short g_r2l[(size_t)MT * NB2];   // r2 lo fp16
__device__ float g_qkv[(size_t)MT * 3 * C_];         // (B*T, 384)
__device__ float g_G[B_ * NCH * C_ * C_];            // per-chunk outer-product sums
__device__ float g_M[B_ * NCH * C_ * C_];            // chunk-boundary states

__device__ __forceinline__ float sigmoidf_(float x) { return 1.0f / (1.0f + expf(-x)); }

__device__ __forceinline__ void mma_f16(float* c, const uint32_t* a, const uint32_t* b) {
    asm volatile(
        "mma.sync.aligned.m16n8k16.row.col.f32.f16.f16.f32 "
        "{%0,%1,%2,%3}, {%4,%5,%6,%7}, {%8,%9}, {%0,%1,%2,%3};"
        : "+f"(c[0]), "+f"(c[1]), "+f"(c[2]), "+f"(c[3])
        : "r"(a[0]), "r"(a[1]), "r"(a[2]), "r"(a[3]), "r"(b[0]), "r"(b[1]));
}

__device__ __forceinline__ uint32_t smem_to_u32(const void* p) {
    uint32_t a;
    asm("{ .reg .u64 t; cvta.to.shared.u64 t, %1; cvt.u32.u64 %0, t; }" : "=r"(a) : "l"(p));
    return a;
}

__device__ __forceinline__ void ldsm_x4(uint32_t* r, uint32_t addr) {
    asm volatile("ldmatrix.sync.aligned.m8n8.x4.shared.b16 {%0,%1,%2,%3}, [%4];"
                 : "=r"(r[0]), "=r"(r[1]), "=r"(r[2]), "=r"(r[3]) : "r"(addr));
}

#define CP_ASYNC16(dst, src) \
    asm volatile("cp.async.cg.shared.global [%0], [%1], 16;" :: "r"(dst), "l"(src))
#define CP_COMMIT() asm volatile("cp.async.commit_group;" ::: "memory")
#define CP_WAIT0()  asm volatile("cp.async.wait_group 0;" ::: "memory")
#define CP_WAIT1()  asm volatile("cp.async.wait_group 1;" ::: "memory")

// ---------------- 0a) convert x to fp16 (single), row-major [M][K] ----------------
__global__ __launch_bounds__(256) void cvt_x_kernel(const float* __restrict__ x) {
    const size_t i = ((size_t)blockIdx.x * 256 + threadIdx.x) * 4;
    float4 v = *(const float4*)(x + i);
    float vv[4] = {v.x, v.y, v.z, v.w};
    unsigned short h[4];
    #pragma unroll
    for (int u = 0; u < 4; u++) h[u] = __half_as_ushort(__float2half_rn(vv[u]));
    *(uint2*)(g_x16 + i) = make_uint2((uint32_t)h[0] | ((uint32_t)h[1] << 16),
                                      (uint32_t)h[2] | ((uint32_t)h[3] << 16));
}

// ---------------- 0b) convert basis to fp16 [N][K] ----------------
__global__ __launch_bounds__(256) void cvt_basis_kernel(const float* __restrict__ basis) {
    const size_t i = ((size_t)blockIdx.x * 256 + threadIdx.x) * 4;
    float4 v = *(const float4*)(basis + i);
    float vv[4] = {v.x, v.y, v.z, v.w};
    unsigned short h[4];
    #pragma unroll
    for (int u = 0; u < 4; u++) h[u] = __half_as_ushort(__float2half_rn(vv[u]));
    *(uint2*)(g_bt + i) = make_uint2((uint32_t)h[0] | ((uint32_t)h[1] << 16),
                                     (uint32_t)h[2] | ((uint32_t)h[3] << 16));
}

// ---------------- 1a) logits = coeffs @ basis^T, written [N][V] ----------------
__global__ __launch_bounds__(256) void logits_kernel(const float* __restrict__ basis,
                                                     const float* __restrict__ qc,
                                                     const float* __restrict__ kc,
                                                     const float* __restrict__ vc) {
    const int w = blockIdx.x;
    const int vb = blockIdx.y;
    const float* coef = (w == 0 ? qc : (w == 1 ? kc : vc));

    __shared__ float Cs[NB2][C_ + 4];
    __shared__ float Bs[NB2][C_ + 4];

    const int tid = threadIdx.x;
    const int lr = tid >> 1;
    const int lk = (tid & 1) * 32;

    #pragma unroll
    for (int u = 0; u < 8; u++) {
        const int k = lk + u * 4;
        float4 cv = *(const float4*)(coef + (size_t)lr * NB2 + k);
        Cs[k + 0][lr] = cv.x; Cs[k + 1][lr] = cv.y;
        Cs[k + 2][lr] = cv.z; Cs[k + 3][lr] = cv.w;
        float4 bv = *(const float4*)(basis + (size_t)(vb * 128 + lr) * NB2 + k);
        Bs[k + 0][lr] = bv.x; Bs[k + 1][lr] = bv.y;
        Bs[k + 2][lr] = bv.z; Bs[k + 3][lr] = bv.w;
    }
    __syncthreads();

    const int trow = tid >> 4;
    const int tcol = tid & 15;
    float acc[8][8] = {};
    #pragma unroll
    for (int kk = 0; kk < NB2; kk++) {
        float ar[8], br[8];
        *(float4*)&ar[0] = *(const float4*)&Cs[kk][trow * 8];
        *(float4*)&ar[4] = *(const float4*)&Cs[kk][trow * 8 + 4];
        *(float4*)&br[0] = *(const float4*)&Bs[kk][tcol * 8];
        *(float4*)&br[4] = *(const float4*)&Bs[kk][tcol * 8 + 4];
        #pragma unroll
        for (int i = 0; i < 8; i++)
            #pragma unroll
            for (int jn = 0; jn < 8; jn++)
                acc[i][jn] = fmaf(ar[i], br[jn], acc[i][jn]);
    }
    #pragma unroll
    for (int i = 0; i < 8; i++) {
        float* lrow = g_logits + (size_t)(w * C_ + trow * 8 + i) * V_ + vb * 128 + tcol * 8;
        *(float4*)(lrow)     = make_float4(acc[i][0], acc[i][1], acc[i][2], acc[i][3]);
        *(float4*)(lrow + 4) = make_float4(acc[i][4], acc[i][5], acc[i][6], acc[i][7]);
    }
}

// ---------------- 1b) column softmax over V, emit fp16 [N][K] ----------------
__global__ __launch_bounds__(256) void softmax_w_kernel() {
    const int n = blockIdx.x;
    const int tid = threadIdx.x;
    __shared__ float red[8];
    __shared__ float sval;

    float4 s4 = *(const float4*)(g_logits + (size_t)n * V_ + tid * 4);
    float s[4] = {s4.x, s4.y, s4.z, s4.w};

    float m = fmaxf(fmaxf(s[0], s[1]), fmaxf(s[2], s[3]));
    #pragma unroll
    for (int o = 16; o; o >>= 1) m = fmaxf(m, __shfl_xor_sync(0xffffffffu, m, o));
    if ((tid & 31) == 0) red[tid >> 5] = m;
    __syncthreads();
    if (tid < 8) {
        float t = red[tid];
        #pragma unroll
        for (int o = 4; o; o >>= 1) t = fmaxf(t, __shfl_xor_sync(0xffu, t, o));
        if (tid == 0) sval = t;
    }
    __syncthreads();
    const float M = sval;

    float e[4];
    float su = 0.f;
    #pragma unroll
    for (int u = 0; u < 4; u++) { e[u] = expf(s[u] - M); su += e[u]; }
    #pragma unroll
    for (int o = 16; o; o >>= 1) su += __shfl_xor_sync(0xffffffffu, su, o);
    if ((tid & 31) == 0) red[tid >> 5] = su;
    __syncthreads();
    if (tid < 8) {
        float t = red[tid];
        #pragma unroll
        for (int o = 4; o; o >>= 1) t += __shfl_xor_sync(0xffu, t, o);
        if (tid == 0) sval = t;
    }
    __syncthreads();
    const float inv = 1.0f / sval;

    unsigned short h[4];
    #pragma unroll
    for (int u = 0; u < 4; u++)
        h[u] = __half_as_ushort(__float2half_rn(e[u] * inv));
    *(uint2*)(g_wt + (size_t)n * V_ + tid * 4) =
        make_uint2((uint32_t)h[0] | ((uint32_t)h[1] << 16),
                   (uint32_t)h[2] | ((uint32_t)h[3] << 16));
}

// ---------------- 2) QKV GEMM: fp16 single-term mma.sync (unchanged from R15) ----------------
#define QKVBUF 16384
__global__ __launch_bounds__(256) void qkv_mma_kernel() {
    extern __shared__ char sm[];
    const uint32_t sbase = smem_to_u32(sm);
    const int tid = threadIdx.x;
    const int warp = tid >> 5, lane = tid & 31;
    const int bm = blockIdx.y * 128;
    const int bn = blockIdx.x * 128;
    const int wm = (warp >> 2) * 64;
    const int wn = (warp & 3) * 32;

    const int frow = tid >> 2;
    const int fkq = tid & 3;

    const int arow = lane & 15;
    const int akg = lane >> 4;
    const int fA = (arow >> 1) & 3;
    const int brow = ((lane >> 4) & 1) * 8 + (lane & 7);
    const int bkg = (lane >> 3) & 1;
    const int fB = (brow >> 1) & 3;

    float acc[4][4][4] = {};

    auto fill = [&](int stage, int c0) {
        const uint32_t nb = sbase + stage * QKVBUF;
        #pragma unroll
        for (int it = 0; it < 2; it++) {
            const int row = frow + it * 64;
            const uint32_t dst = nb + row * 64 + ((fkq ^ ((row >> 1) & 3)) * 16);
            CP_ASYNC16(dst,        g_x16 + (size_t)(bm + row) * V_ + c0 + fkq * 8);
            CP_ASYNC16(dst + 8192, g_wt + (size_t)(bn + row) * V_ + c0 + fkq * 8);
        }
    };

    fill(0, 0);  CP_COMMIT();
    fill(1, 32); CP_COMMIT();

    for (int ch = 0; ch < 32; ch++) {
        CP_WAIT1();
        __syncthreads();

        const uint32_t cb = sbase + (ch % 3) * QKVBUF;
        #pragma unroll
        for (int ks = 0; ks < 2; ks++) {
            uint32_t a_f[4][4];
            const uint32_t achunk = (uint32_t)(((ks * 2 + akg) ^ fA) * 16);
            #pragma unroll
            for (int mi = 0; mi < 4; mi++) {
                const uint32_t aaddr = cb + (uint32_t)((wm + mi * 16 + arow) * 64) + achunk;
                ldsm_x4(a_f[mi], aaddr);
            }
            uint32_t b_f[4][2];
            const uint32_t bchunk = (uint32_t)(((ks * 2 + bkg) ^ fB) * 16);
            #pragma unroll
            for (int nip = 0; nip < 2; nip++) {
                const uint32_t baddr = cb + 8192 +
                    (uint32_t)((wn + nip * 16 + brow) * 64) + bchunk;
                uint32_t rh[4];
                ldsm_x4(rh, baddr);
                b_f[nip * 2 + 0][0] = rh[0]; b_f[nip * 2 + 0][1] = rh[1];
                b_f[nip * 2 + 1][0] = rh[2]; b_f[nip * 2 + 1][1] = rh[3];
            }
            #pragma unroll
            for (int mi = 0; mi < 4; mi++)
                #pragma unroll
                for (int ni = 0; ni < 4; ni++)
                    mma_f16(acc[mi][ni], a_f[mi], b_f[ni]);
        }

        __syncthreads();
        if (ch + 2 < 32) fill((ch + 2) % 3, (ch + 2) * 32);
        CP_COMMIT();
    }

    const int g = lane >> 2, tg = lane & 3;
    #pragma unroll
    for (int mi = 0; mi < 4; mi++) {
        const int r0 = bm + wm + mi * 16 + g;
        #pragma unroll
        for (int ni = 0; ni < 4; ni++) {
            const int col = bn + wn + ni * 8 + tg * 2;
            *(float2*)(g_qkv + (size_t)r0 * (3 * C_) + col) =
                make_float2(acc[mi][ni][0], acc[mi][ni][1]);
            *(float2*)(g_qkv + (size_t)(r0 + 8) * (3 * C_) + col) =
                make_float2(acc[mi][ni][2], acc[mi][ni][3]);
        }
    }
}

// ---------------- 3a) per-chunk outer-product sums, merged 128x128 (fp32, unchanged) ----------------
__global__ __launch_bounds__(256) void chunk_g_kernel(const float* __restrict__ decay_ptr) {
    const int j = blockIdx.x;
    const int b = blockIdx.y;
    const float dec = sigmoidf_(decay_ptr[0]);
    const float l2d = log2f(dec);

    __shared__ float Ks[32][128];
    __shared__ float Vs[32][128];

    const int tid = threadIdx.x;
    const int trow = tid >> 4;
    const int tcol = tid & 15;
    const int r = tid >> 3;
    const int q8 = tid & 7;

    float acc[8][8] = {};
    const float* base = g_qkv + ((size_t)b * T_ + (size_t)j * S_) * (3 * C_);

    #pragma unroll
    for (int i0 = 0; i0 < S_; i0 += 32) {
        const float sc = exp2f((float)(S_ - 1 - (i0 + r)) * l2d);
        const float* row = base + (size_t)(i0 + r) * (3 * C_);
        #pragma unroll
        for (int u = 0; u < 4; u++) {
            const int c4 = (q8 + u * 8) * 4;
            float4 kv = *(const float4*)(row + C_ + c4);
            Ks[r][c4 + 0] = kv.x * sc;
            Ks[r][c4 + 1] = kv.y * sc;
            Ks[r][c4 + 2] = kv.z * sc;
            Ks[r][c4 + 3] = kv.w * sc;
            *(float4*)&Vs[r][c4] = *(const float4*)(row + 2 * C_ + c4);
        }
        __syncthreads();
        #pragma unroll
        for (int ii = 0; ii < 32; ii++) {
            float ar[8], br[8];
            *(float4*)&ar[0] = *(const float4*)&Ks[ii][trow * 8];
            *(float4*)&ar[4] = *(const float4*)&Ks[ii][trow * 8 + 4];
            *(float4*)&br[0] = *(const float4*)&Vs[ii][tcol * 8];
            *(float4*)&br[4] = *(const float4*)&Vs[ii][tcol * 8 + 4];
            #pragma unroll
            for (int m = 0; m < 8; m++)
                #pragma unroll
                for (int n = 0; n < 8; n++)
                    acc[m][n] = fmaf(ar[m], br[n], acc[m][n]);
        }
        __syncthreads();
    }

    float* gout = g_G + ((size_t)(b * NCH + j) * C_ * C_);
    #pragma unroll
    for (int m = 0; m < 8; m++) {
        float* grow = gout + (size_t)(trow * 8 + m) * C_ + tcol * 8;
        *(float4*)(grow)     = make_float4(acc[m][0], acc[m][1], acc[m][2], acc[m][3]);
        *(float4*)(grow + 4) = make_float4(acc[m][4], acc[m][5], acc[m][6], acc[m][7]);
    }
}

// ---------------- 3b) scan, float2 per thread ----------------
__global__ void scan_kernel(const float* __restrict__ decay_ptr) {
    const int idx = blockIdx.x * blockDim.x + threadIdx.x;
    const int b = idx >> 13;
    const int e2 = idx & 8191;
    const float dec = sigmoidf_(decay_ptr[0]);
    const float dS = exp2f((float)S_ * log2f(dec));

    const float2* G = (const float2*)(g_G + (size_t)b * NCH * C_ * C_) + e2;
    float2* M = (float2*)(g_M + (size_t)b * NCH * C_ * C_) + e2;

    float2 m = make_float2(0.f, 0.f);
    #pragma unroll
    for (int jb = 0; jb < NCH; jb += 8) {
        float2 buf[8];
        #pragma unroll
        for (int u = 0; u < 8; u++) buf[u] = G[(size_t)(jb + u) * 8192];
        #pragma unroll
        for (int u = 0; u < 8; u++) {
            M[(size_t)(jb + u) * 8192] = m;
            m.x = fmaf(dS, m.x, buf[u].x);
            m.y = fmaf(dS, m.y, buf[u].y);
        }
    }
}

// ---------------- 3c) retrieval per chunk: fp16 MMA phases + fused r2 = R @ oc ----------------
// Dynamic smem 57344 B:
//   Q  [0,16384): 4 half-tiles [64][32] fp16 (k=c)
//   K  [16384,32768): same (phase1 only); Mt [16384,49152): 4x[128][32] (phase3);
//   Vt [16384,32768): 2x[128][32] (phase2); As [49152,57344): 2x[64][32]
//   Rs fp32 [64][132] at [0,33792) for epilogue.
#define RQOFF  0u
#define RKOFF  16384u
#define RMTOFF 16384u
#define RVTOFF 16384u
#define RASOFF 49152u
#define RSMEM  57344
__global__ __launch_bounds__(256) void retr_kernel(const float* __restrict__ decay_ptr,
                                                   const float* __restrict__ oc) {
    extern __shared__ char sm[];
    const uint32_t sb = smem_to_u32(sm);
    const int j = blockIdx.x;
    const int b = blockIdx.y;
    const float dec = sigmoidf_(decay_ptr[0]);
    const float l2d = log2f(dec);

    const int tid = threadIdx.x;
    const int warp = tid >> 5, lane = tid & 31;
    const int g = lane >> 2, tg = lane & 3;
    const int arow = lane & 15;
    const int akg = lane >> 4;
    const int fA = (arow >> 1) & 3;
    const int brow = ((lane >> 4) & 1) * 8 + (lane & 7);
    const int bkg = (lane >> 3) & 1;
    const int fB = (brow >> 1) & 3;

    const float* base = g_qkv + ((size_t)b * T_ + (size_t)j * S_) * (3 * C_);

    // ---- fill Q and K fp16 tiles ----
    {
        const int row = tid & 63;
        const int q4 = tid >> 6;   // col quarter 0..3 (half index)
        #pragma unroll
        for (int u = 0; u < 8; u++) {
            const int c0 = q4 * 32 + u * 4;
            float4 qv = *(const float4*)(base + (size_t)row * 384 + c0);
            float4 kv = *(const float4*)(base + (size_t)row * 384 + 128 + c0);
            float qa[4] = {qv.x, qv.y, qv.z, qv.w};
            float ka[4] = {kv.x, kv.y, kv.z, kv.w};
            unsigned short qh[4], kh[4];
            #pragma unroll
            for (int e = 0; e < 4; e++) {
                qh[e] = __half_as_ushort(__float2half_rn(qa[e]));
                kh[e] = __half_as_ushort(__float2half_rn(ka[e]));
            }
            const uint32_t off = (uint32_t)(q4 * 4096 + row * 64 +
                (((u >> 1) ^ ((row >> 1) & 3)) * 16) + (u & 1) * 8);
            *(uint2*)(sm + RQOFF + off) = make_uint2(
                (uint32_t)qh[0] | ((uint32_t)qh[1] << 16),
                (uint32_t)qh[2] | ((uint32_t)qh[3] << 16));
            *(uint2*)(sm + RKOFF + off) = make_uint2(
                (uint32_t)kh[0] | ((uint32_t)kh[1] << 16),
                (uint32_t)kh[2] | ((uint32_t)kh[3] << 16));
        }
    }
    __syncthreads();

    // ---- phase 1: S = Q K^T (64x64x128), mask+decay -> As fp16 ----
    {
        const int wm1 = (warp >> 1) * 16, wn1 = (warp & 1) * 32;
        float acc1[4][4] = {};
        #pragma unroll
        for (int h = 0; h < 4; h++) {
            #pragma unroll
            for (int ks = 0; ks < 2; ks++) {
                uint32_t a_f[4];
                const uint32_t achunk = (uint32_t)(((ks * 2 + akg) ^ fA) * 16);
                ldsm_x4(a_f, sb + RQOFF + h * 4096 + (uint32_t)((wm1 + arow) * 64) + achunk);
                uint32_t b_f[4][2];
                const uint32_t bchunk = (uint32_t)(((ks * 2 + bkg) ^ fB) * 16);
                #pragma unroll
                for (int nip = 0; nip < 2; nip++) {
                    uint32_t rh[4];
                    ldsm_x4(rh, sb + RKOFF + h * 4096 +
                            (uint32_t)((wn1 + nip * 16 + brow) * 64) + bchunk);
                    b_f[nip * 2 + 0][0] = rh[0]; b_f[nip * 2 + 0][1] = rh[1];
                    b_f[nip * 2 + 1][0] = rh[2]; b_f[nip * 2 + 1][1] = rh[3];
                }
                #pragma unroll
                for (int ni = 0; ni < 4; ni++)
                    mma_f16(acc1[ni], a_f, b_f[ni]);
            }
        }
        const int half = warp & 1;   // s0 >> 5
        #pragma unroll
        for (int ni = 0; ni < 4; ni++) {
            const int s0 = wn1 + ni * 8 + tg * 2;
            const int sp = s0 & 31;
            #pragma unroll
            for (int rr = 0; rr < 2; rr++) {
                const int i = wm1 + g + rr * 8;
                float v0 = (s0 < i) ? acc1[ni][rr * 2 + 0] * exp2f((float)(i - 1 - s0) * l2d) : 0.f;
                float v1 = (s0 + 1 < i) ? acc1[ni][rr * 2 + 1] * exp2f((float)(i - 2 - s0) * l2d) : 0.f;
                const uint32_t p = (uint32_t)__half_as_ushort(__float2half_rn(v0)) |
                                   ((uint32_t)__half_as_ushort(__float2half_rn(v1)) << 16);
                const uint32_t off = RASOFF + half * 4096 + (uint32_t)(i * 64) +
                    (uint32_t)((((sp >> 3) ^ ((i >> 1) & 3)) * 16) + (sp & 7) * 2);
                *(uint32_t*)(sm + off) = p;
            }
        }
    }
    __syncthreads();

    // ---- fill Mt = M^T fp16 (overwrites K region) ----
    {
        const float* Mb = g_M + (size_t)(b * NCH + j) * C_ * C_;
        const int c = tid & 127;
        const int dq = tid >> 7;   // 0..1
        const int half = c >> 5, cp = c & 31;
        const uint32_t cpart = (uint32_t)((cp >> 3) * 16 + (cp & 7) * 2);
        #pragma unroll
        for (int u = 0; u < 16; u++) {
            const int d0 = dq * 4 + u * 8;
            float4 mv = *(const float4*)(Mb + (size_t)c * C_ + d0);
            float vv[4] = {mv.x, mv.y, mv.z, mv.w};
            #pragma unroll
            for (int e = 0; e < 4; e++) {
                const int d = d0 + e;
                const uint32_t chunkrot = (uint32_t)(((d >> 1) & 3) * 16);
                const uint32_t off = RMTOFF + half * 8192 + (uint32_t)(d * 64) +
                    ((cpart & ~48u) | ((cpart ^ chunkrot) & 48u));
                *(unsigned short*)(sm + off) = __half_as_ushort(__float2half_rn(vv[e]));
            }
        }
    }
    __syncthreads();

    // ---- phase 3: acc = (Q @ Mt), then scale rows by d^i ----
    const int wm = (warp >> 2) * 32;
    const int wn = (warp & 3) * 32;
    float acc[2][4][4] = {};
    {
        #pragma unroll
        for (int h = 0; h < 4; h++) {
            #pragma unroll
            for (int ks = 0; ks < 2; ks++) {
                uint32_t a_f[2][4];
                const uint32_t achunk = (uint32_t)(((ks * 2 + akg) ^ fA) * 16);
                #pragma unroll
                for (int mi = 0; mi < 2; mi++)
                    ldsm_x4(a_f[mi], sb + RQOFF + h * 4096 +
                            (uint32_t)((wm + mi * 16 + arow) * 64) + achunk);
                uint32_t b_f[4][2];
                const uint32_t bchunk = (uint32_t)(((ks * 2 + bkg) ^ fB) * 16);
                #pragma unroll
                for (int nip = 0; nip < 2; nip++) {
                    uint32_t rh[4];
                    ldsm_x4(rh, sb + RMTOFF + h * 8192 +
                            (uint32_t)((wn + nip * 16 + brow) * 64) + bchunk);
                    b_f[nip * 2 + 0][0] = rh[0]; b_f[nip * 2 + 0][1] = rh[1];
                    b_f[nip * 2 + 1][0] = rh[2]; b_f[nip * 2 + 1][1] = rh[3];
                }
                #pragma unroll
                for (int mi = 0; mi < 2; mi++)
                    #pragma unroll
                    for (int ni = 0; ni < 4; ni++)
                        mma_f16(acc[mi][ni], a_f[mi], b_f[ni]);
            }
        }
        #pragma unroll
        for (int mi = 0; mi < 2; mi++) {
            const float d0 = exp2f((float)(wm + mi * 16 + g) * l2d);
            const float d1 = exp2f((float)(wm + mi * 16 + g + 8) * l2d);
            #pragma unroll
            for (int ni = 0; ni < 4; ni++) {
                acc[mi][ni][0] *= d0; acc[mi][ni][1] *= d0;
                acc[mi][ni][2] *= d1; acc[mi][ni][3] *= d1;
            }
        }
    }
    __syncthreads();

    // ---- fill Vt = V^T fp16 (overwrites Mt low region) ----
    {
        const int s = tid & 63;
        const int dq = tid >> 6;   // 0..3
        const int half = s >> 5, spp = s & 31;
        const uint32_t spart = (uint32_t)((spp >> 3) * 16 + (spp & 7) * 2);
        #pragma unroll
        for (int u = 0; u < 8; u++) {
            const int d0 = dq * 4 + u * 16;
            float4 v4 = *(const float4*)(base + (size_t)s * 384 + 256 + d0);
            float vv[4] = {v4.x, v4.y, v4.z, v4.w};
            #pragma unroll
            for (int e = 0; e < 4; e++) {
                const int d = d0 + e;
                const uint32_t chunkrot = (uint32_t)(((d >> 1) & 3) * 16);
                const uint32_t off = RVTOFF + half * 8192 + (uint32_t)(d * 64) +
                    ((spart & ~48u) | ((spart ^ chunkrot) & 48u));
                *(unsigned short*)(sm + off) = __half_as_ushort(__float2half_rn(vv[e]));
            }
        }
    }
    __syncthreads();

    // ---- phase 2: acc += As @ Vt (64x128x64) ----
    {
        #pragma unroll
        for (int h = 0; h < 2; h++) {
            #pragma unroll
            for (int ks = 0; ks < 2; ks++) {
                uint32_t a_f[2][4];
                const uint32_t achunk = (uint32_t)(((ks * 2 + akg) ^ fA) * 16);
                #pragma unroll
                for (int mi = 0; mi < 2; mi++)
                    ldsm_x4(a_f[mi], sb + RASOFF + h * 4096 +
                            (uint32_t)((wm + mi * 16 + arow) * 64) + achunk);
                uint32_t b_f[4][2];
                const uint32_t bchunk = (uint32_t)(((ks * 2 + bkg) ^ fB) * 16);
                #pragma unroll
                for (int nip = 0; nip < 2; nip++) {
                    uint32_t rh[4];
                    ldsm_x4(rh, sb + RVTOFF + h * 8192 +
                            (uint32_t)((wn + nip * 16 + brow) * 64) + bchunk);
                    b_f[nip * 2 + 0][0] = rh[0]; b_f[nip * 2 + 0][1] = rh[1];
                    b_f[nip * 2 + 1][0] = rh[2]; b_f[nip * 2 + 1][1] = rh[3];
                }
                #pragma unroll
                for (int mi = 0; mi < 2; mi++)
                    #pragma unroll
                    for (int ni = 0; ni < 4; ni++)
                        mma_f16(acc[mi][ni], a_f[mi], b_f[ni]);
            }
        }
    }
    __syncthreads();   // Q/As/Vt reads done; Rs overwrites

    // ---- write R to Rs fp32 [64][132] ----
    float* Rs = (float*)sm;
    #pragma unroll
    for (int mi = 0; mi < 2; mi++) {
        const int i0 = wm + mi * 16 + g;
        #pragma unroll
        for (int ni = 0; ni < 4; ni++) {
            const int d0 = wn + ni * 8 + tg * 2;
            *(float2*)&Rs[i0 * 132 + d0]       = make_float2(acc[mi][ni][0], acc[mi][ni][1]);
            *(float2*)&Rs[(i0 + 8) * 132 + d0] = make_float2(acc[mi][ni][2], acc[mi][ni][3]);
        }
    }
    __syncthreads();

    // ---- fused r2 = R (64x128) @ oc (128x64), emit fp16 hi/lo ----
    {
        const int i0 = (tid >> 4) * 4;
        const int j0 = (tid & 15) * 4;
        float racc[4][4] = {};
        #pragma unroll 4
        for (int d4 = 0; d4 < 128; d4 += 4) {
            float4 a0 = *(const float4*)&Rs[(i0 + 0) * 132 + d4];
            float4 a1 = *(const float4*)&Rs[(i0 + 1) * 132 + d4];
            float4 a2 = *(const float4*)&Rs[(i0 + 2) * 132 + d4];
            float4 a3 = *(const float4*)&Rs[(i0 + 3) * 132 + d4];
            float am[4][4] = {{a0.x, a0.y, a0.z, a0.w},
                              {a1.x, a1.y, a1.z, a1.w},
                              {a2.x, a2.y, a2.z, a2.w},
                              {a3.x, a3.y, a3.z, a3.w}};
            #pragma unroll
            for (int dd = 0; dd < 4; dd++) {
                float4 bv = __ldg((const float4*)(oc + (size_t)(d4 + dd) * NB2 + j0));
                float br[4] = {bv.x, bv.y, bv.z, bv.w};
                #pragma unroll
                for (int ii = 0; ii < 4; ii++)
                    #pragma unroll
                    for (int jj = 0; jj < 4; jj++)
                        racc[ii][jj] = fmaf(am[ii][dd], br[jj], racc[ii][jj]);
            }
        }
        const size_t mbase = (size_t)b * T_ + (size_t)j * S_;
        #pragma unroll
        for (int ii = 0; ii < 4; ii++) {
            unsigned short h[4], l[4];
            #pragma unroll
            for (int jj = 0; jj < 4; jj++) {
                __half hb = __float2half_rn(racc[ii][jj]);
                __half lb = __float2half_rn(racc[ii][jj] - __half2float(hb));
                h[jj] = __half_as_ushort(hb);
                l[jj] = __half_as_ushort(lb);
            }
            const size_t o = (mbase + i0 + ii) * NB2 + j0;
            *(uint2*)(g_r2h + o) = make_uint2((uint32_t)h[0] | ((uint32_t)h[1] << 16),
                                              (uint32_t)h[2] | ((uint32_t)h[3] << 16));
            *(uint2*)(g_r2l + o) = make_uint2((uint32_t)l[0] | ((uint32_t)l[1] << 16),
                                              (uint32_t)l[2] | ((uint32_t)l[3] << 16));
        }
    }
}

// ---------------- 4) out = r2 @ basis^T * scale, fp16 2-term (unchanged) ----------------
#define OBUF 24576
__global__ __launch_bounds__(256) void out2_mma_kernel(float* __restrict__ Cout,
                                                       const float* __restrict__ scale_ptr) {
    extern __shared__ char sm[];
    const uint32_t sbase = smem_to_u32(sm);
    const int tid = threadIdx.x;
    const int warp = tid >> 5, lane = tid & 31;
    const int bm = blockIdx.y * 128;
    const int bn = blockIdx.x * 128;
    const int wm = (warp >> 2) * 64;
    const int wn = (warp & 3) * 32;

    const int frow = tid >> 2;
    const int fkq = tid & 3;

    const int arow = lane & 15;
    const int akg = lane >> 4;
    const int fA = (arow >> 1) & 3;
    const int brow = ((lane >> 4) & 1) * 8 + (lane & 7);
    const int bkg = (lane >> 3) & 1;
    const int fB = (brow >> 1) & 3;

    float acc[4][4][4] = {};

    auto fill = [&](int stage, int c0) {
        const uint32_t nb = sbase + stage * OBUF;
        #pragma unroll
        for (int it = 0; it < 2; it++) {
            const int row = frow + it * 64;
            const uint32_t dst = nb + row * 64 + ((fkq ^ ((row >> 1) & 3)) * 16);
            CP_ASYNC16(dst,         g_r2h + (size_t)(bm + row) * NB2 + c0 + fkq * 8);
            CP_ASYNC16(dst + 8192,  g_r2l + (size_t)(bm + row) * NB2 + c0 + fkq * 8);
            CP_ASYNC16(dst + 16384, g_bt + (size_t)(bn + row) * NB2 + c0 + fkq * 8);
        }
    };

    fill(0, 0);
    CP_COMMIT();

    for (int ch = 0; ch < 2; ch++) {
        if (ch + 1 < 2) { fill(ch + 1, 32); CP_COMMIT(); }
        if (ch == 0) { CP_WAIT1(); } else { CP_WAIT0(); }
        __syncthreads();

        const uint32_t cb = sbase + ch * OBUF;
        #pragma unroll
        for (int ks = 0; ks < 2; ks++) {
            uint32_t a_h[4][4], a_l[4][4];
            const uint32_t achunk = (uint32_t)(((ks * 2 + akg) ^ fA) * 16);
            #pragma unroll
            for (int mi = 0; mi < 4; mi++) {
                const uint32_t aaddr = cb + (uint32_t)((wm + mi * 16 + arow) * 64) + achunk;
                ldsm_x4(a_h[mi], aaddr);
                ldsm_x4(a_l[mi], aaddr + 8192);
            }
            uint32_t b_f[4][2];
            const uint32_t bchunk = (uint32_t)(((ks * 2 + bkg) ^ fB) * 16);
            #pragma unroll
            for (int nip = 0; nip < 2; nip++) {
                const uint32_t baddr = cb + 16384 +
                    (uint32_t)((wn + nip * 16 + brow) * 64) + bchunk;
                uint32_t rh[4];
                ldsm_x4(rh, baddr);
                b_f[nip * 2 + 0][0] = rh[0]; b_f[nip * 2 + 0][1] = rh[1];
                b_f[nip * 2 + 1][0] = rh[2]; b_f[nip * 2 + 1][1] = rh[3];
            }
            #pragma unroll
            for (int mi = 0; mi < 4; mi++)
                #pragma unroll
                for (int ni = 0; ni < 4; ni++) {
                    mma_f16(acc[mi][ni], a_l[mi], b_f[ni]);
                    mma_f16(acc[mi][ni], a_h[mi], b_f[ni]);
                }
        }
        __syncthreads();
    }

    const float sc = *scale_ptr;
    const int g = lane >> 2, tg = lane & 3;
    #pragma unroll
    for (int mi = 0; mi < 4; mi++) {
        const int r0 = bm + wm + mi * 16 + g;
        #pragma unroll
        for (int ni = 0; ni < 4; ni++) {
            const int col = bn + wn + ni * 8 + tg * 2;
            *(float2*)(Cout + (size_t)r0 * V_ + col) =
                make_float2(acc[mi][ni][0] * sc, acc[mi][ni][1] * sc);
            *(float2*)(Cout + (size_t)(r0 + 8) * V_ + col) =
                make_float2(acc[mi][ni][2] * sc, acc[mi][ni][3] * sc);
        }
    }
}

// ---------------- launch ----------------
extern "C" void kernel_launch(void* const* d_in, const int* in_sizes, int n_in,
                              void* d_out, int out_size) {
    const float* x      = (const float*)d_in[0];
    const float* basis  = (const float*)d_in[1];
    const float* qc     = (const float*)d_in[2];
    const float* kc     = (const float*)d_in[3];
    const float* vc     = (const float*)d_in[4];
    const float* oc     = (const float*)d_in[5];
    const float* decay  = (const float*)d_in[6];
    const float* oscale = (const float*)d_in[7];
    float* out = (float*)d_out;

    cudaFuncSetAttribute(qkv_mma_kernel, cudaFuncAttributeMaxDynamicSharedMemorySize, 3 * QKVBUF);
    cudaFuncSetAttribute(retr_kernel, cudaFuncAttributeMaxDynamicSharedMemorySize, RSMEM);
    cudaFuncSetAttribute(out2_mma_kernel, cudaFuncAttributeMaxDynamicSharedMemorySize, 2 * OBUF);

    cvt_x_kernel<<<(MT * V_) / 1024, 256>>>(x);
    cvt_basis_kernel<<<(V_ * NB2) / 1024, 256>>>(basis);
    logits_kernel<<<dim3(3, 8), 256>>>(basis, qc, kc, vc);
    softmax_w_kernel<<<3 * C_, 256>>>();
    qkv_mma_kernel<<<dim3(3, MT / 128), 256, 3 * QKVBUF>>>();
    chunk_g_kernel<<<dim3(NCH, B_), 256>>>(decay);
    scan_kernel<<<256, 256>>>(decay);
    retr_kernel<<<dim3(NCH, B_), 256, RSMEM>>>(decay, oc);
    out2_mma_kernel<<<dim3(V_ / 128, MT / 128), 256, 2 * OBUF>>>(out, oscale);
}

// round 17
// speedup vs baseline: 1.8247x; 1.0760x over previous
#include <cuda_runtime.h>
#include <cuda_fp16.h>
#include <math.h>
#include <stdint.h>

#define B_ 8
#define T_ 2048
#define V_ 1024
#define C_ 128
#define NB2 64   // 2*NB
#define S_ 64    // chunk size
#define NCH 32   // T_/S_
#define MT (B_ * T_)   // 16384

// ---------------- device scratch ----------------
__device__ unsigned short g_x16[(size_t)MT * V_];    // x fp16 (single), row-major [M][K]
__device__ unsigned short g_wt[3 * C_ * V_];         // W^T fp16 (single), [N][K]
__device__ float g_logits[3 * C_ * V_];              // logits [N][V]
__device__ unsigned short g_bt[V_ * NB2];            // basis fp16 (single) [N][K]
__device__ unsigned short g_r2h[(size_t)MT * NB2];   // r2 hi fp16 [M][64]
__device__ unsigned short g_r2l[(size_t)MT * NB2];   // r2 lo fp16
__device__ float g_qkv[(size_t)MT * 3 * C_];         // (B*T, 384)
__device__ float g_G[B_ * NCH * C_ * C_];            // per-chunk outer-product sums
__device__ float g_M[B_ * NCH * C_ * C_];            // chunk-boundary states

__device__ __forceinline__ float sigmoidf_(float x) { return 1.0f / (1.0f + expf(-x)); }

__device__ __forceinline__ void mma_f16(float* c, const uint32_t* a, const uint32_t* b) {
    asm volatile(
        "mma.sync.aligned.m16n8k16.row.col.f32.f16.f16.f32 "
        "{%0,%1,%2,%3}, {%4,%5,%6,%7}, {%8,%9}, {%0,%1,%2,%3};"
        : "+f"(c[0]), "+f"(c[1]), "+f"(c[2]), "+f"(c[3])
        : "r"(a[0]), "r"(a[1]), "r"(a[2]), "r"(a[3]), "r"(b[0]), "r"(b[1]));
}

__device__ __forceinline__ uint32_t smem_to_u32(const void* p) {
    uint32_t a;
    asm("{ .reg .u64 t; cvta.to.shared.u64 t, %1; cvt.u32.u64 %0, t; }" : "=r"(a) : "l"(p));
    return a;
}

__device__ __forceinline__ void ldsm_x4(uint32_t* r, uint32_t addr) {
    asm volatile("ldmatrix.sync.aligned.m8n8.x4.shared.b16 {%0,%1,%2,%3}, [%4];"
                 : "=r"(r[0]), "=r"(r[1]), "=r"(r[2]), "=r"(r[3]) : "r"(addr));
}

#define CP_ASYNC16(dst, src) \
    asm volatile("cp.async.cg.shared.global [%0], [%1], 16;" :: "r"(dst), "l"(src))
#define CP_COMMIT() asm volatile("cp.async.commit_group;" ::: "memory")
#define CP_WAIT0()  asm volatile("cp.async.wait_group 0;" ::: "memory")
#define CP_WAIT1()  asm volatile("cp.async.wait_group 1;" ::: "memory")

// ---------------- 0a) convert x to fp16 (single), row-major [M][K] ----------------
__global__ __launch_bounds__(256) void cvt_x_kernel(const float* __restrict__ x) {
    const size_t i = ((size_t)blockIdx.x * 256 + threadIdx.x) * 4;
    float4 v = *(const float4*)(x + i);
    float vv[4] = {v.x, v.y, v.z, v.w};
    unsigned short h[4];
    #pragma unroll
    for (int u = 0; u < 4; u++) h[u] = __half_as_ushort(__float2half_rn(vv[u]));
    *(uint2*)(g_x16 + i) = make_uint2((uint32_t)h[0] | ((uint32_t)h[1] << 16),
                                      (uint32_t)h[2] | ((uint32_t)h[3] << 16));
}

// ---------------- 0b) convert basis to fp16 [N][K] ----------------
__global__ __launch_bounds__(256) void cvt_basis_kernel(const float* __restrict__ basis) {
    const size_t i = ((size_t)blockIdx.x * 256 + threadIdx.x) * 4;
    float4 v = *(const float4*)(basis + i);
    float vv[4] = {v.x, v.y, v.z, v.w};
    unsigned short h[4];
    #pragma unroll
    for (int u = 0; u < 4; u++) h[u] = __half_as_ushort(__float2half_rn(vv[u]));
    *(uint2*)(g_bt + i) = make_uint2((uint32_t)h[0] | ((uint32_t)h[1] << 16),
                                     (uint32_t)h[2] | ((uint32_t)h[3] << 16));
}

// ---------------- 1a) logits = coeffs @ basis^T, written [N][V] ----------------
__global__ __launch_bounds__(256) void logits_kernel(const float* __restrict__ basis,
                                                     const float* __restrict__ qc,
                                                     const float* __restrict__ kc,
                                                     const float* __restrict__ vc) {
    const int w = blockIdx.x;
    const int vb = blockIdx.y;
    const float* coef = (w == 0 ? qc : (w == 1 ? kc : vc));

    __shared__ float Cs[NB2][C_ + 4];
    __shared__ float Bs[NB2][C_ + 4];

    const int tid = threadIdx.x;
    const int lr = tid >> 1;
    const int lk = (tid & 1) * 32;

    #pragma unroll
    for (int u = 0; u < 8; u++) {
        const int k = lk + u * 4;
        float4 cv = *(const float4*)(coef + (size_t)lr * NB2 + k);
        Cs[k + 0][lr] = cv.x; Cs[k + 1][lr] = cv.y;
        Cs[k + 2][lr] = cv.z; Cs[k + 3][lr] = cv.w;
        float4 bv = *(const float4*)(basis + (size_t)(vb * 128 + lr) * NB2 + k);
        Bs[k + 0][lr] = bv.x; Bs[k + 1][lr] = bv.y;
        Bs[k + 2][lr] = bv.z; Bs[k + 3][lr] = bv.w;
    }
    __syncthreads();

    const int trow = tid >> 4;
    const int tcol = tid & 15;
    float acc[8][8] = {};
    #pragma unroll
    for (int kk = 0; kk < NB2; kk++) {
        float ar[8], br[8];
        *(float4*)&ar[0] = *(const float4*)&Cs[kk][trow * 8];
        *(float4*)&ar[4] = *(const float4*)&Cs[kk][trow * 8 + 4];
        *(float4*)&br[0] = *(const float4*)&Bs[kk][tcol * 8];
        *(float4*)&br[4] = *(const float4*)&Bs[kk][tcol * 8 + 4];
        #pragma unroll
        for (int i = 0; i < 8; i++)
            #pragma unroll
            for (int jn = 0; jn < 8; jn++)
                acc[i][jn] = fmaf(ar[i], br[jn], acc[i][jn]);
    }
    #pragma unroll
    for (int i = 0; i < 8; i++) {
        float* lrow = g_logits + (size_t)(w * C_ + trow * 8 + i) * V_ + vb * 128 + tcol * 8;
        *(float4*)(lrow)     = make_float4(acc[i][0], acc[i][1], acc[i][2], acc[i][3]);
        *(float4*)(lrow + 4) = make_float4(acc[i][4], acc[i][5], acc[i][6], acc[i][7]);
    }
}

// ---------------- 1b) column softmax, warp-per-row, emit fp16 [N][K] ----------------
__global__ __launch_bounds__(256) void softmax_w_kernel() {
    const int n = blockIdx.x * 8 + (threadIdx.x >> 5);
    const int lane = threadIdx.x & 31;
    const float* lrow = g_logits + (size_t)n * V_;

    float4 v[8];
    float m = -1e30f;
    #pragma unroll
    for (int u = 0; u < 8; u++) {
        v[u] = *(const float4*)(lrow + (size_t)(u * 32 + lane) * 4);
        m = fmaxf(m, fmaxf(fmaxf(v[u].x, v[u].y), fmaxf(v[u].z, v[u].w)));
    }
    #pragma unroll
    for (int o = 16; o; o >>= 1) m = fmaxf(m, __shfl_xor_sync(0xffffffffu, m, o));

    float su = 0.f;
    #pragma unroll
    for (int u = 0; u < 8; u++) {
        v[u].x = expf(v[u].x - m); v[u].y = expf(v[u].y - m);
        v[u].z = expf(v[u].z - m); v[u].w = expf(v[u].w - m);
        su += v[u].x + v[u].y + v[u].z + v[u].w;
    }
    #pragma unroll
    for (int o = 16; o; o >>= 1) su += __shfl_xor_sync(0xffffffffu, su, o);
    const float inv = 1.0f / su;

    #pragma unroll
    for (int u = 0; u < 8; u++) {
        unsigned short h[4];
        h[0] = __half_as_ushort(__float2half_rn(v[u].x * inv));
        h[1] = __half_as_ushort(__float2half_rn(v[u].y * inv));
        h[2] = __half_as_ushort(__float2half_rn(v[u].z * inv));
        h[3] = __half_as_ushort(__float2half_rn(v[u].w * inv));
        *(uint2*)(g_wt + (size_t)n * V_ + (size_t)(u * 32 + lane) * 4) =
            make_uint2((uint32_t)h[0] | ((uint32_t)h[1] << 16),
                       (uint32_t)h[2] | ((uint32_t)h[3] << 16));
    }
}

// ---------------- 2) QKV GEMM: fp16 single-term mma.sync (unchanged) ----------------
#define QKVBUF 16384
__global__ __launch_bounds__(256) void qkv_mma_kernel() {
    extern __shared__ char sm[];
    const uint32_t sbase = smem_to_u32(sm);
    const int tid = threadIdx.x;
    const int warp = tid >> 5, lane = tid & 31;
    const int bm = blockIdx.y * 128;
    const int bn = blockIdx.x * 128;
    const int wm = (warp >> 2) * 64;
    const int wn = (warp & 3) * 32;

    const int frow = tid >> 2;
    const int fkq = tid & 3;

    const int arow = lane & 15;
    const int akg = lane >> 4;
    const int fA = (arow >> 1) & 3;
    const int brow = ((lane >> 4) & 1) * 8 + (lane & 7);
    const int bkg = (lane >> 3) & 1;
    const int fB = (brow >> 1) & 3;

    float acc[4][4][4] = {};

    auto fill = [&](int stage, int c0) {
        const uint32_t nb = sbase + stage * QKVBUF;
        #pragma unroll
        for (int it = 0; it < 2; it++) {
            const int row = frow + it * 64;
            const uint32_t dst = nb + row * 64 + ((fkq ^ ((row >> 1) & 3)) * 16);
            CP_ASYNC16(dst,        g_x16 + (size_t)(bm + row) * V_ + c0 + fkq * 8);
            CP_ASYNC16(dst + 8192, g_wt + (size_t)(bn + row) * V_ + c0 + fkq * 8);
        }
    };

    fill(0, 0);  CP_COMMIT();
    fill(1, 32); CP_COMMIT();

    for (int ch = 0; ch < 32; ch++) {
        CP_WAIT1();
        __syncthreads();

        const uint32_t cb = sbase + (ch % 3) * QKVBUF;
        #pragma unroll
        for (int ks = 0; ks < 2; ks++) {
            uint32_t a_f[4][4];
            const uint32_t achunk = (uint32_t)(((ks * 2 + akg) ^ fA) * 16);
            #pragma unroll
            for (int mi = 0; mi < 4; mi++) {
                const uint32_t aaddr = cb + (uint32_t)((wm + mi * 16 + arow) * 64) + achunk;
                ldsm_x4(a_f[mi], aaddr);
            }
            uint32_t b_f[4][2];
            const uint32_t bchunk = (uint32_t)(((ks * 2 + bkg) ^ fB) * 16);
            #pragma unroll
            for (int nip = 0; nip < 2; nip++) {
                const uint32_t baddr = cb + 8192 +
                    (uint32_t)((wn + nip * 16 + brow) * 64) + bchunk;
                uint32_t rh[4];
                ldsm_x4(rh, baddr);
                b_f[nip * 2 + 0][0] = rh[0]; b_f[nip * 2 + 0][1] = rh[1];
                b_f[nip * 2 + 1][0] = rh[2]; b_f[nip * 2 + 1][1] = rh[3];
            }
            #pragma unroll
            for (int mi = 0; mi < 4; mi++)
                #pragma unroll
                for (int ni = 0; ni < 4; ni++)
                    mma_f16(acc[mi][ni], a_f[mi], b_f[ni]);
        }

        __syncthreads();
        if (ch + 2 < 32) fill((ch + 2) % 3, (ch + 2) * 32);
        CP_COMMIT();
    }

    const int g = lane >> 2, tg = lane & 3;
    #pragma unroll
    for (int mi = 0; mi < 4; mi++) {
        const int r0 = bm + wm + mi * 16 + g;
        #pragma unroll
        for (int ni = 0; ni < 4; ni++) {
            const int col = bn + wn + ni * 8 + tg * 2;
            *(float2*)(g_qkv + (size_t)r0 * (3 * C_) + col) =
                make_float2(acc[mi][ni][0], acc[mi][ni][1]);
            *(float2*)(g_qkv + (size_t)(r0 + 8) * (3 * C_) + col) =
                make_float2(acc[mi][ni][2], acc[mi][ni][3]);
        }
    }
}

// ---------------- 3a) per-chunk G = K^T_scaled @ V via fp16 MMA ----------------
// Kt/Vt: transposed [c|d][i] fp16, 2 half-tiles [128][32] each (8 KB/tile).
__global__ __launch_bounds__(256) void chunk_g_kernel(const float* __restrict__ decay_ptr) {
    __shared__ char sm[32768];
    const uint32_t sb = smem_to_u32(sm);
    const int j = blockIdx.x;
    const int b = blockIdx.y;
    const float dec = sigmoidf_(decay_ptr[0]);
    const float l2d = log2f(dec);

    const int tid = threadIdx.x;
    const int warp = tid >> 5, lane = tid & 31;
    const int g = lane >> 2, tg = lane & 3;
    const int arow = lane & 15;
    const int akg = lane >> 4;
    const int fA = (arow >> 1) & 3;
    const int brow = ((lane >> 4) & 1) * 8 + (lane & 7);
    const int bkg = (lane >> 3) & 1;
    const int fB = (brow >> 1) & 3;

    const float* base = g_qkv + ((size_t)b * T_ + (size_t)j * S_) * (3 * C_);

    // ---- fill Kt (scaled) and Vt, transposed swizzled fp16 ----
    {
        const int i = tid >> 2;          // 0..63 (k row)
        const int q4 = tid & 3;
        const float sc = exp2f((float)(S_ - 1 - i) * l2d);
        const int h = i >> 5, ip = i & 31;
        const uint32_t ipart = (uint32_t)((ip >> 3) * 16 + (ip & 7) * 2);
        #pragma unroll
        for (int u = 0; u < 8; u++) {
            const int c0 = q4 * 4 + u * 16;
            float4 kv = *(const float4*)(base + (size_t)i * 384 + 128 + c0);
            float4 vv = *(const float4*)(base + (size_t)i * 384 + 256 + c0);
            float ka[4] = {kv.x, kv.y, kv.z, kv.w};
            float va[4] = {vv.x, vv.y, vv.z, vv.w};
            #pragma unroll
            for (int e = 0; e < 4; e++) {
                const int c = c0 + e;
                const uint32_t chunkrot = (uint32_t)(((c >> 1) & 3) * 16);
                const uint32_t off = (uint32_t)(h * 8192 + c * 64) +
                    ((ipart & ~48u) | ((ipart ^ chunkrot) & 48u));
                *(unsigned short*)(sm + off)         = __half_as_ushort(__float2half_rn(ka[e] * sc));
                *(unsigned short*)(sm + 16384 + off) = __half_as_ushort(__float2half_rn(va[e]));
            }
        }
    }
    __syncthreads();

    // ---- MMA: G[128][128] = Kt @ Vt^T style (both [row][k]); warp tile 64x32 ----
    const int wm = (warp >> 2) * 64;
    const int wn = (warp & 3) * 32;
    float acc[4][4][4] = {};
    #pragma unroll
    for (int h2 = 0; h2 < 2; h2++) {
        #pragma unroll
        for (int ks = 0; ks < 2; ks++) {
            uint32_t a_f[4][4];
            const uint32_t achunk = (uint32_t)(((ks * 2 + akg) ^ fA) * 16);
            #pragma unroll
            for (int mi = 0; mi < 4; mi++)
                ldsm_x4(a_f[mi], sb + (uint32_t)(h2 * 8192) +
                        (uint32_t)((wm + mi * 16 + arow) * 64) + achunk);
            uint32_t b_f[4][2];
            const uint32_t bchunk = (uint32_t)(((ks * 2 + bkg) ^ fB) * 16);
            #pragma unroll
            for (int nip = 0; nip < 2; nip++) {
                uint32_t rh[4];
                ldsm_x4(rh, sb + 16384u + (uint32_t)(h2 * 8192) +
                        (uint32_t)((wn + nip * 16 + brow) * 64) + bchunk);
                b_f[nip * 2 + 0][0] = rh[0]; b_f[nip * 2 + 0][1] = rh[1];
                b_f[nip * 2 + 1][0] = rh[2]; b_f[nip * 2 + 1][1] = rh[3];
            }
            #pragma unroll
            for (int mi = 0; mi < 4; mi++)
                #pragma unroll
                for (int ni = 0; ni < 4; ni++)
                    mma_f16(acc[mi][ni], a_f[mi], b_f[ni]);
        }
    }

    float* gout = g_G + ((size_t)(b * NCH + j) * C_ * C_);
    #pragma unroll
    for (int mi = 0; mi < 4; mi++) {
        const int r0 = wm + mi * 16 + g;
        #pragma unroll
        for (int ni = 0; ni < 4; ni++) {
            const int col = wn + ni * 8 + tg * 2;
            *(float2*)(gout + (size_t)r0 * C_ + col) =
                make_float2(acc[mi][ni][0], acc[mi][ni][1]);
            *(float2*)(gout + (size_t)(r0 + 8) * C_ + col) =
                make_float2(acc[mi][ni][2], acc[mi][ni][3]);
        }
    }
}

// ---------------- 3b) scan, float2 per thread ----------------
__global__ void scan_kernel(const float* __restrict__ decay_ptr) {
    const int idx = blockIdx.x * blockDim.x + threadIdx.x;
    const int b = idx >> 13;
    const int e2 = idx & 8191;
    const float dec = sigmoidf_(decay_ptr[0]);
    const float dS = exp2f((float)S_ * log2f(dec));

    const float2* G = (const float2*)(g_G + (size_t)b * NCH * C_ * C_) + e2;
    float2* M = (float2*)(g_M + (size_t)b * NCH * C_ * C_) + e2;

    float2 m = make_float2(0.f, 0.f);
    #pragma unroll
    for (int jb = 0; jb < NCH; jb += 8) {
        float2 buf[8];
        #pragma unroll
        for (int u = 0; u < 8; u++) buf[u] = G[(size_t)(jb + u) * 8192];
        #pragma unroll
        for (int u = 0; u < 8; u++) {
            M[(size_t)(jb + u) * 8192] = m;
            m.x = fmaf(dS, m.x, buf[u].x);
            m.y = fmaf(dS, m.y, buf[u].y);
        }
    }
}

// ---------------- 3c) retrieval per chunk: fp16 MMA phases + fused r2 = R @ oc ----------------
#define RQOFF  0u
#define RKOFF  16384u
#define RMTOFF 16384u
#define RVTOFF 16384u
#define RASOFF 49152u
#define RSMEM  57344
__global__ __launch_bounds__(256) void retr_kernel(const float* __restrict__ decay_ptr,
                                                   const float* __restrict__ oc) {
    extern __shared__ char sm[];
    const uint32_t sb = smem_to_u32(sm);
    const int j = blockIdx.x;
    const int b = blockIdx.y;
    const float dec = sigmoidf_(decay_ptr[0]);
    const float l2d = log2f(dec);

    const int tid = threadIdx.x;
    const int warp = tid >> 5, lane = tid & 31;
    const int g = lane >> 2, tg = lane & 3;
    const int arow = lane & 15;
    const int akg = lane >> 4;
    const int fA = (arow >> 1) & 3;
    const int brow = ((lane >> 4) & 1) * 8 + (lane & 7);
    const int bkg = (lane >> 3) & 1;
    const int fB = (brow >> 1) & 3;

    const float* base = g_qkv + ((size_t)b * T_ + (size_t)j * S_) * (3 * C_);

    // ---- fill Q and K fp16 tiles ----
    {
        const int row = tid & 63;
        const int q4 = tid >> 6;
        #pragma unroll
        for (int u = 0; u < 8; u++) {
            const int c0 = q4 * 32 + u * 4;
            float4 qv = *(const float4*)(base + (size_t)row * 384 + c0);
            float4 kv = *(const float4*)(base + (size_t)row * 384 + 128 + c0);
            float qa[4] = {qv.x, qv.y, qv.z, qv.w};
            float ka[4] = {kv.x, kv.y, kv.z, kv.w};
            unsigned short qh[4], kh[4];
            #pragma unroll
            for (int e = 0; e < 4; e++) {
                qh[e] = __half_as_ushort(__float2half_rn(qa[e]));
                kh[e] = __half_as_ushort(__float2half_rn(ka[e]));
            }
            const uint32_t off = (uint32_t)(q4 * 4096 + row * 64 +
                (((u >> 1) ^ ((row >> 1) & 3)) * 16) + (u & 1) * 8);
            *(uint2*)(sm + RQOFF + off) = make_uint2(
                (uint32_t)qh[0] | ((uint32_t)qh[1] << 16),
                (uint32_t)qh[2] | ((uint32_t)qh[3] << 16));
            *(uint2*)(sm + RKOFF + off) = make_uint2(
                (uint32_t)kh[0] | ((uint32_t)kh[1] << 16),
                (uint32_t)kh[2] | ((uint32_t)kh[3] << 16));
        }
    }
    __syncthreads();

    // ---- phase 1: S = Q K^T, mask+decay -> As fp16 ----
    {
        const int wm1 = (warp >> 1) * 16, wn1 = (warp & 1) * 32;
        float acc1[4][4] = {};
        #pragma unroll
        for (int h = 0; h < 4; h++) {
            #pragma unroll
            for (int ks = 0; ks < 2; ks++) {
                uint32_t a_f[4];
                const uint32_t achunk = (uint32_t)(((ks * 2 + akg) ^ fA) * 16);
                ldsm_x4(a_f, sb + RQOFF + h * 4096 + (uint32_t)((wm1 + arow) * 64) + achunk);
                uint32_t b_f[4][2];
                const uint32_t bchunk = (uint32_t)(((ks * 2 + bkg) ^ fB) * 16);
                #pragma unroll
                for (int nip = 0; nip < 2; nip++) {
                    uint32_t rh[4];
                    ldsm_x4(rh, sb + RKOFF + h * 4096 +
                            (uint32_t)((wn1 + nip * 16 + brow) * 64) + bchunk);
                    b_f[nip * 2 + 0][0] = rh[0]; b_f[nip * 2 + 0][1] = rh[1];
                    b_f[nip * 2 + 1][0] = rh[2]; b_f[nip * 2 + 1][1] = rh[3];
                }
                #pragma unroll
                for (int ni = 0; ni < 4; ni++)
                    mma_f16(acc1[ni], a_f, b_f[ni]);
            }
        }
        const int half = warp & 1;
        #pragma unroll
        for (int ni = 0; ni < 4; ni++) {
            const int s0 = wn1 + ni * 8 + tg * 2;
            const int sp = s0 & 31;
            #pragma unroll
            for (int rr = 0; rr < 2; rr++) {
                const int i = wm1 + g + rr * 8;
                float v0 = (s0 < i) ? acc1[ni][rr * 2 + 0] * exp2f((float)(i - 1 - s0) * l2d) : 0.f;
                float v1 = (s0 + 1 < i) ? acc1[ni][rr * 2 + 1] * exp2f((float)(i - 2 - s0) * l2d) : 0.f;
                const uint32_t p = (uint32_t)__half_as_ushort(__float2half_rn(v0)) |
                                   ((uint32_t)__half_as_ushort(__float2half_rn(v1)) << 16);
                const uint32_t off = RASOFF + half * 4096 + (uint32_t)(i * 64) +
                    (uint32_t)((((sp >> 3) ^ ((i >> 1) & 3)) * 16) + (sp & 7) * 2);
                *(uint32_t*)(sm + off) = p;
            }
        }
    }
    __syncthreads();

    // ---- fill Mt = M^T fp16 ----
    {
        const float* Mb = g_M + (size_t)(b * NCH + j) * C_ * C_;
        const int c = tid & 127;
        const int dq = tid >> 7;
        const int half = c >> 5, cp = c & 31;
        const uint32_t cpart = (uint32_t)((cp >> 3) * 16 + (cp & 7) * 2);
        #pragma unroll
        for (int u = 0; u < 16; u++) {
            const int d0 = dq * 4 + u * 8;
            float4 mv = *(const float4*)(Mb + (size_t)c * C_ + d0);
            float vv[4] = {mv.x, mv.y, mv.z, mv.w};
            #pragma unroll
            for (int e = 0; e < 4; e++) {
                const int d = d0 + e;
                const uint32_t chunkrot = (uint32_t)(((d >> 1) & 3) * 16);
                const uint32_t off = RMTOFF + half * 8192 + (uint32_t)(d * 64) +
                    ((cpart & ~48u) | ((cpart ^ chunkrot) & 48u));
                *(unsigned short*)(sm + off) = __half_as_ushort(__float2half_rn(vv[e]));
            }
        }
    }
    __syncthreads();

    // ---- phase 3: acc = (Q @ Mt), scale rows by d^i ----
    const int wm = (warp >> 2) * 32;
    const int wn = (warp & 3) * 32;
    float acc[2][4][4] = {};
    {
        #pragma unroll
        for (int h = 0; h < 4; h++) {
            #pragma unroll
            for (int ks = 0; ks < 2; ks++) {
                uint32_t a_f[2][4];
                const uint32_t achunk = (uint32_t)(((ks * 2 + akg) ^ fA) * 16);
                #pragma unroll
                for (int mi = 0; mi < 2; mi++)
                    ldsm_x4(a_f[mi], sb + RQOFF + h * 4096 +
                            (uint32_t)((wm + mi * 16 + arow) * 64) + achunk);
                uint32_t b_f[4][2];
                const uint32_t bchunk = (uint32_t)(((ks * 2 + bkg) ^ fB) * 16);
                #pragma unroll
                for (int nip = 0; nip < 2; nip++) {
                    uint32_t rh[4];
                    ldsm_x4(rh, sb + RMTOFF + h * 8192 +
                            (uint32_t)((wn + nip * 16 + brow) * 64) + bchunk);
                    b_f[nip * 2 + 0][0] = rh[0]; b_f[nip * 2 + 0][1] = rh[1];
                    b_f[nip * 2 + 1][0] = rh[2]; b_f[nip * 2 + 1][1] = rh[3];
                }
                #pragma unroll
                for (int mi = 0; mi < 2; mi++)
                    #pragma unroll
                    for (int ni = 0; ni < 4; ni++)
                        mma_f16(acc[mi][ni], a_f[mi], b_f[ni]);
            }
        }
        #pragma unroll
        for (int mi = 0; mi < 2; mi++) {
            const float d0 = exp2f((float)(wm + mi * 16 + g) * l2d);
            const float d1 = exp2f((float)(wm + mi * 16 + g + 8) * l2d);
            #pragma unroll
            for (int ni = 0; ni < 4; ni++) {
                acc[mi][ni][0] *= d0; acc[mi][ni][1] *= d0;
                acc[mi][ni][2] *= d1; acc[mi][ni][3] *= d1;
            }
        }
    }
    __syncthreads();

    // ---- fill Vt = V^T fp16 ----
    {
        const int s = tid & 63;
        const int dq = tid >> 6;
        const int half = s >> 5, spp = s & 31;
        const uint32_t spart = (uint32_t)((spp >> 3) * 16 + (spp & 7) * 2);
        #pragma unroll
        for (int u = 0; u < 8; u++) {
            const int d0 = dq * 4 + u * 16;
            float4 v4 = *(const float4*)(base + (size_t)s * 384 + 256 + d0);
            float vv[4] = {v4.x, v4.y, v4.z, v4.w};
            #pragma unroll
            for (int e = 0; e < 4; e++) {
                const int d = d0 + e;
                const uint32_t chunkrot = (uint32_t)(((d >> 1) & 3) * 16);
                const uint32_t off = RVTOFF + half * 8192 + (uint32_t)(d * 64) +
                    ((spart & ~48u) | ((spart ^ chunkrot) & 48u));
                *(unsigned short*)(sm + off) = __half_as_ushort(__float2half_rn(vv[e]));
            }
        }
    }
    __syncthreads();

    // ---- phase 2: acc += As @ Vt ----
    {
        #pragma unroll
        for (int h = 0; h < 2; h++) {
            #pragma unroll
            for (int ks = 0; ks < 2; ks++) {
                uint32_t a_f[2][4];
                const uint32_t achunk = (uint32_t)(((ks * 2 + akg) ^ fA) * 16);
                #pragma unroll
                for (int mi = 0; mi < 2; mi++)
                    ldsm_x4(a_f[mi], sb + RASOFF + h * 4096 +
                            (uint32_t)((wm + mi * 16 + arow) * 64) + achunk);
                uint32_t b_f[4][2];
                const uint32_t bchunk = (uint32_t)(((ks * 2 + bkg) ^ fB) * 16);
                #pragma unroll
                for (int nip = 0; nip < 2; nip++) {
                    uint32_t rh[4];
                    ldsm_x4(rh, sb + RVTOFF + h * 8192 +
                            (uint32_t)((wn + nip * 16 + brow) * 64) + bchunk);
                    b_f[nip * 2 + 0][0] = rh[0]; b_f[nip * 2 + 0][1] = rh[1];
                    b_f[nip * 2 + 1][0] = rh[2]; b_f[nip * 2 + 1][1] = rh[3];
                }
                #pragma unroll
                for (int mi = 0; mi < 2; mi++)
                    #pragma unroll
                    for (int ni = 0; ni < 4; ni++)
                        mma_f16(acc[mi][ni], a_f[mi], b_f[ni]);
            }
        }
    }
    __syncthreads();

    // ---- write R to Rs fp32 [64][132] ----
    float* Rs = (float*)sm;
    #pragma unroll
    for (int mi = 0; mi < 2; mi++) {
        const int i0 = wm + mi * 16 + g;
        #pragma unroll
        for (int ni = 0; ni < 4; ni++) {
            const int d0 = wn + ni * 8 + tg * 2;
            *(float2*)&Rs[i0 * 132 + d0]       = make_float2(acc[mi][ni][0], acc[mi][ni][1]);
            *(float2*)&Rs[(i0 + 8) * 132 + d0] = make_float2(acc[mi][ni][2], acc[mi][ni][3]);
        }
    }
    __syncthreads();

    // ---- fused r2 = R @ oc, emit fp16 hi/lo ----
    {
        const int i0 = (tid >> 4) * 4;
        const int j0 = (tid & 15) * 4;
        float racc[4][4] = {};
        #pragma unroll 4
        for (int d4 = 0; d4 < 128; d4 += 4) {
            float4 a0 = *(const float4*)&Rs[(i0 + 0) * 132 + d4];
            float4 a1 = *(const float4*)&Rs[(i0 + 1) * 132 + d4];
            float4 a2 = *(const float4*)&Rs[(i0 + 2) * 132 + d4];
            float4 a3 = *(const float4*)&Rs[(i0 + 3) * 132 + d4];
            float am[4][4] = {{a0.x, a0.y, a0.z, a0.w},
                              {a1.x, a1.y, a1.z, a1.w},
                              {a2.x, a2.y, a2.z, a2.w},
                              {a3.x, a3.y, a3.z, a3.w}};
            #pragma unroll
            for (int dd = 0; dd < 4; dd++) {
                float4 bv = __ldg((const float4*)(oc + (size_t)(d4 + dd) * NB2 + j0));
                float br[4] = {bv.x, bv.y, bv.z, bv.w};
                #pragma unroll
                for (int ii = 0; ii < 4; ii++)
                    #pragma unroll
                    for (int jj = 0; jj < 4; jj++)
                        racc[ii][jj] = fmaf(am[ii][dd], br[jj], racc[ii][jj]);
            }
        }
        const size_t mbase = (size_t)b * T_ + (size_t)j * S_;
        #pragma unroll
        for (int ii = 0; ii < 4; ii++) {
            unsigned short h[4], l[4];
            #pragma unroll
            for (int jj = 0; jj < 4; jj++) {
                __half hb = __float2half_rn(racc[ii][jj]);
                __half lb = __float2half_rn(racc[ii][jj] - __half2float(hb));
                h[jj] = __half_as_ushort(hb);
                l[jj] = __half_as_ushort(lb);
            }
            const size_t o = (mbase + i0 + ii) * NB2 + j0;
            *(uint2*)(g_r2h + o) = make_uint2((uint32_t)h[0] | ((uint32_t)h[1] << 16),
                                              (uint32_t)h[2] | ((uint32_t)h[3] << 16));
            *(uint2*)(g_r2l + o) = make_uint2((uint32_t)l[0] | ((uint32_t)l[1] << 16),
                                              (uint32_t)l[2] | ((uint32_t)l[3] << 16));
        }
    }
}

// ---------------- 4) out = r2 @ basis^T * scale, fp16 2-term (unchanged) ----------------
#define OBUF 24576
__global__ __launch_bounds__(256) void out2_mma_kernel(float* __restrict__ Cout,
                                                       const float* __restrict__ scale_ptr) {
    extern __shared__ char sm[];
    const uint32_t sbase = smem_to_u32(sm);
    const int tid = threadIdx.x;
    const int warp = tid >> 5, lane = tid & 31;
    const int bm = blockIdx.y * 128;
    const int bn = blockIdx.x * 128;
    const int wm = (warp >> 2) * 64;
    const int wn = (warp & 3) * 32;

    const int frow = tid >> 2;
    const int fkq = tid & 3;

    const int arow = lane & 15;
    const int akg = lane >> 4;
    const int fA = (arow >> 1) & 3;
    const int brow = ((lane >> 4) & 1) * 8 + (lane & 7);
    const int bkg = (lane >> 3) & 1;
    const int fB = (brow >> 1) & 3;

    float acc[4][4][4] = {};

    auto fill = [&](int stage, int c0) {
        const uint32_t nb = sbase + stage * OBUF;
        #pragma unroll
        for (int it = 0; it < 2; it++) {
            const int row = frow + it * 64;
            const uint32_t dst = nb + row * 64 + ((fkq ^ ((row >> 1) & 3)) * 16);
            CP_ASYNC16(dst,         g_r2h + (size_t)(bm + row) * NB2 + c0 + fkq * 8);
            CP_ASYNC16(dst + 8192,  g_r2l + (size_t)(bm + row) * NB2 + c0 + fkq * 8);
            CP_ASYNC16(dst + 16384, g_bt + (size_t)(bn + row) * NB2 + c0 + fkq * 8);
        }
    };

    fill(0, 0);
    CP_COMMIT();

    for (int ch = 0; ch < 2; ch++) {
        if (ch + 1 < 2) { fill(ch + 1, 32); CP_COMMIT(); }
        if (ch == 0) { CP_WAIT1(); } else { CP_WAIT0(); }
        __syncthreads();

        const uint32_t cb = sbase + ch * OBUF;
        #pragma unroll
        for (int ks = 0; ks < 2; ks++) {
            uint32_t a_h[4][4], a_l[4][4];
            const uint32_t achunk = (uint32_t)(((ks * 2 + akg) ^ fA) * 16);
            #pragma unroll
            for (int mi = 0; mi < 4; mi++) {
                const uint32_t aaddr = cb + (uint32_t)((wm + mi * 16 + arow) * 64) + achunk;
                ldsm_x4(a_h[mi], aaddr);
                ldsm_x4(a_l[mi], aaddr + 8192);
            }
            uint32_t b_f[4][2];
            const uint32_t bchunk = (uint32_t)(((ks * 2 + bkg) ^ fB) * 16);
            #pragma unroll
            for (int nip = 0; nip < 2; nip++) {
                const uint32_t baddr = cb + 16384 +
                    (uint32_t)((wn + nip * 16 + brow) * 64) + bchunk;
                uint32_t rh[4];
                ldsm_x4(rh, baddr);
                b_f[nip * 2 + 0][0] = rh[0]; b_f[nip * 2 + 0][1] = rh[1];
                b_f[nip * 2 + 1][0] = rh[2]; b_f[nip * 2 + 1][1] = rh[3];
            }
            #pragma unroll
            for (int mi = 0; mi < 4; mi++)
                #pragma unroll
                for (int ni = 0; ni < 4; ni++) {
                    mma_f16(acc[mi][ni], a_l[mi], b_f[ni]);
                    mma_f16(acc[mi][ni], a_h[mi], b_f[ni]);
                }
        }
        __syncthreads();
    }

    const float sc = *scale_ptr;
    const int g = lane >> 2, tg = lane & 3;
    #pragma unroll
    for (int mi = 0; mi < 4; mi++) {
        const int r0 = bm + wm + mi * 16 + g;
        #pragma unroll
        for (int ni = 0; ni < 4; ni++) {
            const int col = bn + wn + ni * 8 + tg * 2;
            *(float2*)(Cout + (size_t)r0 * V_ + col) =
                make_float2(acc[mi][ni][0] * sc, acc[mi][ni][1] * sc);
            *(float2*)(Cout + (size_t)(r0 + 8) * V_ + col) =
                make_float2(acc[mi][ni][2] * sc, acc[mi][ni][3] * sc);
        }
    }
}

// ---------------- launch ----------------
extern "C" void kernel_launch(void* const* d_in, const int* in_sizes, int n_in,
                              void* d_out, int out_size) {
    const float* x      = (const float*)d_in[0];
    const float* basis  = (const float*)d_in[1];
    const float* qc     = (const float*)d_in[2];
    const float* kc     = (const float*)d_in[3];
    const float* vc     = (const float*)d_in[4];
    const float* oc     = (const float*)d_in[5];
    const float* decay  = (const float*)d_in[6];
    const float* oscale = (const float*)d_in[7];
    float* out = (float*)d_out;

    cudaFuncSetAttribute(qkv_mma_kernel, cudaFuncAttributeMaxDynamicSharedMemorySize, 3 * QKVBUF);
    cudaFuncSetAttribute(retr_kernel, cudaFuncAttributeMaxDynamicSharedMemorySize, RSMEM);
    cudaFuncSetAttribute(out2_mma_kernel, cudaFuncAttributeMaxDynamicSharedMemorySize, 2 * OBUF);

    cvt_x_kernel<<<(MT * V_) / 1024, 256>>>(x);
    cvt_basis_kernel<<<(V_ * NB2) / 1024, 256>>>(basis);
    logits_kernel<<<dim3(3, 8), 256>>>(basis, qc, kc, vc);
    softmax_w_kernel<<<(3 * C_) / 8, 256>>>();
    qkv_mma_kernel<<<dim3(3, MT / 128), 256, 3 * QKVBUF>>>();
    chunk_g_kernel<<<dim3(NCH, B_), 256>>>(decay);
    scan_kernel<<<256, 256>>>(decay);
    retr_kernel<<<dim3(NCH, B_), 256, RSMEM>>>(decay, oc);
    out2_mma_kernel<<<dim3(V_ / 128, MT / 128), 256, 2 * OBUF>>>(out, oscale);
}